// round 13
// baseline (speedup 1.0000x reference)
#include <cuda_runtime.h>
#include <cuda_fp16.h>
#include <math.h>
#include <stdint.h>

namespace {
constexpr int B_ = 256;
constexpr int S_ = 128;
constexpr int H_ = 512;
constexpr int E_ = 512;
constexpr int V_ = 32000;
constexpr int IN_ = E_ + 2 * H_;   // 1536
constexpr int G_ = 3 * H_;         // 1536
constexpr int NX_ = V_ / 128;      // 250
}

// ---------------- static scratch ----------------
__device__ float g_gi[B_ * G_];
__device__ float g_gh[B_ * G_];
__device__ float g_hidden[B_ * H_];
__device__ float g_sc[B_ * S_];
__device__ float g_attn[B_ * S_];
__device__ float g_pmax[B_ * NX_];
__device__ float g_psum[B_ * NX_];
__device__ __half g_x_hi[B_ * IN_];
__device__ __half g_x_lo[B_ * IN_];
__device__ __half g_prev_hi[B_ * H_];
__device__ __half g_prev_lo[B_ * H_];
__device__ __half g_wih_hi[G_ * IN_];
__device__ __half g_whh_hi[G_ * H_];
__device__ __half g_wc_hi[H_ * 2 * H_];
__device__ __half g_hid_hi[B_ * H_];
__device__ __half g_hid_lo[B_ * H_];

// ---------------- helpers ----------------
__device__ __forceinline__ void cp_async16(uint32_t s, const void* g) {
    asm volatile("cp.async.cg.shared.global [%0], [%1], 16;\n"
                 :: "r"(s), "l"(g) : "memory");
}
__device__ __forceinline__ void cp_commit() {
    asm volatile("cp.async.commit_group;\n" ::: "memory");
}
template <int N>
__device__ __forceinline__ void cp_wait() {
    asm volatile("cp.async.wait_group %0;\n" :: "n"(N) : "memory");
}
__device__ __forceinline__ uint32_t smem_u32(const void* p) {
    uint32_t a;
    asm("{ .reg .u64 t; cvta.to.shared.u64 t, %1; cvt.u32.u64 %0, t; }"
        : "=r"(a) : "l"(p));
    return a;
}
__device__ __forceinline__ void ldmx4(uint32_t& r0, uint32_t& r1, uint32_t& r2,
                                      uint32_t& r3, uint32_t addr) {
    asm volatile("ldmatrix.sync.aligned.m8n8.x4.shared.b16 {%0,%1,%2,%3}, [%4];\n"
                 : "=r"(r0), "=r"(r1), "=r"(r2), "=r"(r3) : "r"(addr));
}
__device__ __forceinline__ void mma16816(float* d, const uint32_t* a,
                                         const uint32_t* b) {
    asm volatile(
        "mma.sync.aligned.m16n8k16.row.col.f32.f16.f16.f32 "
        "{%0,%1,%2,%3}, {%4,%5,%6,%7}, {%8,%9}, {%0,%1,%2,%3};\n"
        : "+f"(d[0]), "+f"(d[1]), "+f"(d[2]), "+f"(d[3])
        : "r"(a[0]), "r"(a[1]), "r"(a[2]), "r"(a[3]), "r"(b[0]), "r"(b[1]));
}
__device__ __forceinline__ uint32_t f2h2(float2 f) {
    __half2 h = __float22half2_rn(f);
    return *reinterpret_cast<uint32_t*>(&h);
}
__device__ __forceinline__ void split2h(float2 f, uint32_t& hi, uint32_t& lo) {
    hi = f2h2(f);
    __half2 hh = *reinterpret_cast<__half2*>(&hi);
    float2 fh = __half22float2(hh);
    lo = f2h2(make_float2(f.x - fh.x, f.y - fh.y));
}
__device__ __forceinline__ uint2 h4_of(float4 v) {
    return make_uint2(f2h2(make_float2(v.x, v.y)), f2h2(make_float2(v.z, v.w)));
}
__device__ __forceinline__ void hl4_of(float4 v, uint2& h, uint2& l) {
    uint32_t h0, h1, l0, l1;
    split2h(make_float2(v.x, v.y), h0, l0);
    split2h(make_float2(v.z, v.w), h1, l1);
    h = make_uint2(h0, h1); l = make_uint2(l0, l1);
}
__device__ __forceinline__ void msum(float& m, float& s, float om, float os) {
    float nm = fmaxf(m, om);
    s = s * __expf(m - nm) + os * __expf(om - nm);
    m = nm;
}

// =====================================================================
// Fused prep (unchanged from R12)
// =====================================================================
constexpr int PC0 = 96, PC1 = 32, PC2 = 576, PC3 = 192, PC4 = 512, PC5 = 96, PC6 = 8;
constexpr int PREP_CTAS = PC0 + PC1 + PC2 + PC3 + PC4 + PC5 + PC6;

__global__ void __launch_bounds__(256)
prep_kernel(const int* __restrict__ ids, const float* __restrict__ emb,
            const float* __restrict__ weighted, const float* __restrict__ prev,
            const float* __restrict__ w_ih, const float* __restrict__ w_hh,
            const float* __restrict__ Wc_w) {
    int bid = blockIdx.x;
    const int tid = threadIdx.x;
    if (bid < PC0) {
        const int n4 = B_ * IN_ / 4, T = PC0 * 256, J4 = IN_ / 4;
        for (int i = bid * 256 + tid; i < n4; i += T) {
            int b = i / J4, j = (i - b * J4) * 4;
            float4 v = (j < E_)
                ? *reinterpret_cast<const float4*>(emb + (size_t)ids[b] * E_ + j)
                : *reinterpret_cast<const float4*>(weighted + (size_t)b * 2 * H_ + (j - E_));
            uint2 h, l; hl4_of(v, h, l);
            *reinterpret_cast<uint2*>(g_x_hi + (size_t)i * 4) = h;
            *reinterpret_cast<uint2*>(g_x_lo + (size_t)i * 4) = l;
        }
        return;
    }
    bid -= PC0;
    if (bid < PC1) {
        const int n4 = B_ * H_ / 4, T = PC1 * 256;
        const float4* s4 = reinterpret_cast<const float4*>(prev);
        for (int i = bid * 256 + tid; i < n4; i += T) {
            uint2 h, l; hl4_of(s4[i], h, l);
            *reinterpret_cast<uint2*>(g_prev_hi + (size_t)i * 4) = h;
            *reinterpret_cast<uint2*>(g_prev_lo + (size_t)i * 4) = l;
        }
        return;
    }
    bid -= PC1;
    if (bid < PC2) {
        const int n4 = G_ * IN_ / 4, T = PC2 * 256;
        const float4* s4 = reinterpret_cast<const float4*>(w_ih);
        for (int i = bid * 256 + tid; i < n4; i += T)
            *reinterpret_cast<uint2*>(g_wih_hi + (size_t)i * 4) = h4_of(s4[i]);
        return;
    }
    bid -= PC2;
    if (bid < PC3) {
        const int n4 = G_ * H_ / 4, T = PC3 * 256;
        const float4* s4 = reinterpret_cast<const float4*>(w_hh);
        for (int i = bid * 256 + tid; i < n4; i += T)
            *reinterpret_cast<uint2*>(g_whh_hi + (size_t)i * 4) = h4_of(s4[i]);
        return;
    }
    bid -= PC3;
    if (bid < PC4) {
        const int n4 = H_ * 2 * H_ / 4, T = PC4 * 256;
        const float4* s4 = reinterpret_cast<const float4*>(Wc_w);
        for (int i = bid * 256 + tid; i < n4; i += T)
            *reinterpret_cast<uint2*>(g_wc_hi + (size_t)i * 4) = h4_of(s4[i]);
        return;
    }
    bid -= PC4;
    if (bid < PC5) {
        const int n4 = B_ * G_ / 4, T = PC5 * 256;
        float4* p = reinterpret_cast<float4*>(g_gi);
        for (int i = bid * 256 + tid; i < n4; i += T)
            p[i] = make_float4(0.f, 0.f, 0.f, 0.f);
        return;
    }
    bid -= PC5;
    {
        const int n4 = B_ * S_ / 4, T = PC6 * 256;
        float4* p = reinterpret_cast<float4*>(g_sc);
        for (int i = bid * 256 + tid; i < n4; i += T)
            p[i] = make_float4(0.f, 0.f, 0.f, 0.f);
    }
}

// ---------------- common GEMM constants ----------------
constexpr int ROWB = 80;
constexpr int HTILE = 128 * ROWB;          // 10240 B (128-row fp16 tile)
constexpr int ATILE2 = 256 * ROWB;         // 20480 B (256-row fp16 tile)

// =====================================================================
// Gates (unchanged from R12): gi split-K z=0..2 + gh z=3
// =====================================================================
constexpr int GATES_SMEM = 3 * 3 * HTILE;

__global__ void __launch_bounds__(256, 2)
mma_gates(const float* __restrict__ b_ih, const float* __restrict__ b_hh) {
    extern __shared__ __align__(16) char smem[];
    const int t = threadIdx.x;
    const int lane = t & 31;
    const int wid = t >> 5;
    const int wm = wid & 3, wn = wid >> 2;
    const int m0 = blockIdx.y * 128, n0 = blockIdx.x * 128;
    const int z = blockIdx.z;
    const uint32_t sb = smem_u32(smem);

    const __half *Ah, *Al, *Bh;
    const float* bias;
    float* C;
    int K, kstart;
    bool atomic, addBias;
    if (z < 3) {
        Ah = g_x_hi; Al = g_x_lo; Bh = g_wih_hi;
        bias = b_ih; C = g_gi; K = IN_; kstart = z * 512;
        atomic = true; addBias = (z == 0);
    } else {
        Ah = g_prev_hi; Al = g_prev_lo; Bh = g_whh_hi;
        bias = b_hh; C = g_gh; K = H_; kstart = 0;
        atomic = false; addBias = true;
    }
    const int KCH = 16;

    float acc[2][8][4];
#pragma unroll
    for (int i = 0; i < 2; i++)
#pragma unroll
        for (int j = 0; j < 8; j++)
#pragma unroll
            for (int r = 0; r < 4; r++) acc[i][j][r] = 0.f;

    auto issue = [&](int it) {
        uint32_t st = sb + (uint32_t)(it % 3) * (3 * HTILE);
        int kk = kstart + it * 32;
#pragma unroll
        for (int i = 0; i < 2; i++) {
            int idx = t + i * 256;
            int row = idx >> 2, col = idx & 3;
            uint32_t so = (uint32_t)(row * ROWB + col * 16);
            const size_t ga = (size_t)(m0 + row) * K + kk + col * 8;
            const size_t gb = (size_t)(n0 + row) * K + kk + col * 8;
            cp_async16(st + so, Ah + ga);
            cp_async16(st + HTILE + so, Al + ga);
            cp_async16(st + 2 * HTILE + so, Bh + gb);
        }
        cp_commit();
    };

    const int a_row = (lane & 15);
    const int a_kof = ((lane >> 4) & 1) * 16;
    const int b_row = ((lane >> 4) << 3) + (lane & 7);
    const int b_kof = ((lane >> 3) & 1) * 16;
    const int g = lane >> 2, q = lane & 3;

    issue(0); issue(1);
    for (int it = 0; it < KCH; ++it) {
        if (it + 1 < KCH) cp_wait<1>(); else cp_wait<0>();
        __syncthreads();
        if (it + 2 < KCH) issue(it + 2);
        const uint32_t st = sb + (uint32_t)(it % 3) * (3 * HTILE);
#pragma unroll
        for (int ks = 0; ks < 2; ks++) {
            const int kb = ks * 32;
            uint32_t bh[8][2];
#pragma unroll
            for (int njp = 0; njp < 4; njp++) {
                uint32_t addr = st + 2 * HTILE + (wn * 64 + njp * 16 + b_row) * ROWB + kb + b_kof;
                uint32_t q0, q1, q2, q3;
                ldmx4(q0, q1, q2, q3, addr);
                bh[njp * 2][0] = q0; bh[njp * 2][1] = q1;
                bh[njp * 2 + 1][0] = q2; bh[njp * 2 + 1][1] = q3;
            }
#pragma unroll
            for (int mi = 0; mi < 2; mi++) {
                const uint32_t aro = (wm * 32 + mi * 16 + a_row) * ROWB + kb + a_kof;
                uint32_t ah[4], al[4];
                ldmx4(ah[0], ah[1], ah[2], ah[3], st + aro);
                ldmx4(al[0], al[1], al[2], al[3], st + HTILE + aro);
#pragma unroll
                for (int nj = 0; nj < 8; nj++) mma16816(acc[mi][nj], ah, bh[nj]);
#pragma unroll
                for (int nj = 0; nj < 8; nj++) mma16816(acc[mi][nj], al, bh[nj]);
            }
        }
    }

#pragma unroll
    for (int mi = 0; mi < 2; mi++) {
        int row0 = m0 + wm * 32 + mi * 16 + g;
        int row1 = row0 + 8;
#pragma unroll
        for (int nj = 0; nj < 8; nj++) {
            int col = n0 + wn * 64 + nj * 8 + 2 * q;
            float b0 = addBias ? bias[col] : 0.f;
            float b1 = addBias ? bias[col + 1] : 0.f;
            if (atomic) {
                atomicAdd(&C[(size_t)row0 * G_ + col],     acc[mi][nj][0] + b0);
                atomicAdd(&C[(size_t)row0 * G_ + col + 1], acc[mi][nj][1] + b1);
                atomicAdd(&C[(size_t)row1 * G_ + col],     acc[mi][nj][2] + b0);
                atomicAdd(&C[(size_t)row1 * G_ + col + 1], acc[mi][nj][3] + b1);
            } else {
                float2 o0 = make_float2(acc[mi][nj][0] + b0, acc[mi][nj][1] + b1);
                float2 o1 = make_float2(acc[mi][nj][2] + b0, acc[mi][nj][3] + b1);
                *reinterpret_cast<float2*>(&C[(size_t)row0 * G_ + col]) = o0;
                *reinterpret_cast<float2*>(&C[(size_t)row1 * G_ + col]) = o1;
            }
        }
    }
}

// =====================================================================
// Merged scores kernel, CTA tile 256x128, warp tile 64x64 (mi=4, nj=8).
// blocks [0, 512) -> score_c (bx=bid&3, by=bid>>2)
// blocks [512, 762) -> score_g (bx = bid-512, M=256 in one tile)
// =====================================================================
constexpr uint32_t SC_BOFF = 2 * ATILE2;          // 40960
constexpr int SC_SMEM = SC_BOFF + 3 * HTILE;      // 71680
constexpr uint32_t SG_BOFF = 2 * 2 * ATILE2;      // 81920 (2 stages x hi/lo)
constexpr int SG_SMEM = SG_BOFF + 2 * HTILE;      // 102400
constexpr int SCORES_SMEM = SG_SMEM;
constexpr int SC_CTAS = (B_ * S_ / 256) * 4;      // 512
constexpr int SG_CTAS = NX_;                      // 250

__device__ void sc_body(char* smem, int bx, int by,
                        const float* __restrict__ Af, const __half* __restrict__ Bh16,
                        const float* __restrict__ bias,
                        const float* __restrict__ hidden, float* __restrict__ scOut) {
    const int K = 2 * H_;   // 1024
    const int t = threadIdx.x;
    const int lane = t & 31;
    const int wid = t >> 5;
    const int wm = wid & 3, wn = wid >> 2;   // 4 x 64-row, 2 x 64-col
    const int m0 = by * 256, n0 = bx * 128;
    const uint32_t sb = smem_u32(smem);

    float acc[4][8][4];
#pragma unroll
    for (int i = 0; i < 4; i++)
#pragma unroll
        for (int j = 0; j < 8; j++)
#pragma unroll
            for (int r = 0; r < 4; r++) acc[i][j][r] = 0.f;

    const int KT = K / 32;   // 32
    const float* Abase = Af + (size_t)(m0 + t) * K;   // one row per thread

    float4 r4[8];
    auto ldgA = [&](int it) {
        const float* p = Abase + it * 32;
#pragma unroll
        for (int i = 0; i < 8; i++) r4[i] = *reinterpret_cast<const float4*>(p + i * 4);
    };
    auto stsA = [&](int buf) {
        uint32_t h[16];
#pragma unroll
        for (int i = 0; i < 8; i++) {
            h[i * 2]     = f2h2(make_float2(r4[i].x, r4[i].y));
            h[i * 2 + 1] = f2h2(make_float2(r4[i].z, r4[i].w));
        }
        uint32_t d = (uint32_t)buf * ATILE2 + (uint32_t)(t * ROWB);
        *reinterpret_cast<uint4*>(smem + d)      = make_uint4(h[0], h[1], h[2], h[3]);
        *reinterpret_cast<uint4*>(smem + d + 16) = make_uint4(h[4], h[5], h[6], h[7]);
        *reinterpret_cast<uint4*>(smem + d + 32) = make_uint4(h[8], h[9], h[10], h[11]);
        *reinterpret_cast<uint4*>(smem + d + 48) = make_uint4(h[12], h[13], h[14], h[15]);
    };
    auto issueB = [&](int it) {
        uint32_t bt = sb + SC_BOFF + (uint32_t)(it % 3) * HTILE;
        int kk = it * 32;
#pragma unroll
        for (int i = 0; i < 2; i++) {
            int idx = t + i * 256;
            int row = idx >> 2, col = idx & 3;
            cp_async16(bt + (uint32_t)(row * ROWB + col * 16),
                       Bh16 + (size_t)(n0 + row) * K + kk + col * 8);
        }
        cp_commit();
    };

    const int a_row = (lane & 15);
    const int a_kof = ((lane >> 4) & 1) * 16;
    const int b_row = ((lane >> 4) << 3) + (lane & 7);
    const int b_kof = ((lane >> 3) & 1) * 16;
    const int g = lane >> 2, q = lane & 3;

    issueB(0); issueB(1);
    ldgA(0);
    cp_wait<1>();
    stsA(0);
    __syncthreads();

    for (int it = 0; it < KT; ++it) {
        if (it + 1 < KT) ldgA(it + 1);
        if (it + 2 < KT) issueB(it + 2);

        const uint32_t aT = sb + (uint32_t)(it & 1) * ATILE2;
        const uint32_t bT = sb + SC_BOFF + (uint32_t)(it % 3) * HTILE;
#pragma unroll
        for (int ks = 0; ks < 2; ks++) {
            const int kb = ks * 32;
            uint32_t bh[8][2];
#pragma unroll
            for (int njp = 0; njp < 4; njp++) {
                uint32_t addr = bT + (wn * 64 + njp * 16 + b_row) * ROWB + kb + b_kof;
                uint32_t q0, q1, q2, q3;
                ldmx4(q0, q1, q2, q3, addr);
                bh[njp * 2][0] = q0; bh[njp * 2][1] = q1;
                bh[njp * 2 + 1][0] = q2; bh[njp * 2 + 1][1] = q3;
            }
#pragma unroll
            for (int mi = 0; mi < 4; mi++) {
                const uint32_t aro = (wm * 64 + mi * 16 + a_row) * ROWB + kb + a_kof;
                uint32_t ah[4];
                ldmx4(ah[0], ah[1], ah[2], ah[3], aT + aro);
#pragma unroll
                for (int nj = 0; nj < 8; nj++) mma16816(acc[mi][nj], ah, bh[nj]);
            }
        }
        if (it + 1 < KT) {
            if (it + 2 < KT) cp_wait<1>(); else cp_wait<0>();
            stsA((it + 1) & 1);
        }
        __syncthreads();
    }

    // epilogue: tanh + dot(hidden) + reduce + atomic
#pragma unroll
    for (int mi = 0; mi < 4; mi++) {
        int row0 = m0 + wm * 64 + mi * 16 + g;
        const int b = row0 >> 7;
        float p0 = 0.f, p1 = 0.f;
#pragma unroll
        for (int nj = 0; nj < 8; nj++) {
            int col = n0 + wn * 64 + nj * 8 + 2 * q;
            float bz0 = bias[col], bz1 = bias[col + 1];
            float hv0 = hidden[b * H_ + col], hv1 = hidden[b * H_ + col + 1];
            p0 = fmaf(tanhf(acc[mi][nj][0] + bz0), hv0, p0);
            p0 = fmaf(tanhf(acc[mi][nj][1] + bz1), hv1, p0);
            p1 = fmaf(tanhf(acc[mi][nj][2] + bz0), hv0, p1);
            p1 = fmaf(tanhf(acc[mi][nj][3] + bz1), hv1, p1);
        }
        p0 += __shfl_xor_sync(0xffffffffu, p0, 1);
        p0 += __shfl_xor_sync(0xffffffffu, p0, 2);
        p1 += __shfl_xor_sync(0xffffffffu, p1, 1);
        p1 += __shfl_xor_sync(0xffffffffu, p1, 2);
        if (q == 0) {
            atomicAdd(&scOut[row0], p0);
            atomicAdd(&scOut[row0 + 8], p1);
        }
    }
}

__device__ void sg_body(char* smem, int bx,
                        const __half* __restrict__ Ah, const __half* __restrict__ Al,
                        const float* __restrict__ Bf, const float* __restrict__ bias,
                        float* __restrict__ C) {
    const int K = H_, N = V_;
    const int t = threadIdx.x;
    const int lane = t & 31;
    const int wid = t >> 5;
    const int wm = wid & 3, wn = wid >> 2;
    const int n0 = bx * 128;
    const uint32_t sb = smem_u32(smem);

    float acc[4][8][4];
#pragma unroll
    for (int i = 0; i < 4; i++)
#pragma unroll
        for (int j = 0; j < 8; j++)
#pragma unroll
            for (int r = 0; r < 4; r++) acc[i][j][r] = 0.f;

    const int KT = K / 32;   // 16
    const int br = t >> 1, bhf = t & 1;
    const float* Bbase = Bf + (size_t)(n0 + br) * K + bhf * 16;

    float4 r4[4];
    auto ldgB = [&](int it) {
        const float* p = Bbase + it * 32;
#pragma unroll
        for (int i = 0; i < 4; i++) r4[i] = *reinterpret_cast<const float4*>(p + i * 4);
    };
    auto stsB = [&](int buf) {
        uint32_t h[8];
#pragma unroll
        for (int i = 0; i < 4; i++) {
            h[i * 2]     = f2h2(make_float2(r4[i].x, r4[i].y));
            h[i * 2 + 1] = f2h2(make_float2(r4[i].z, r4[i].w));
        }
        uint32_t d = SG_BOFF + (uint32_t)buf * HTILE + (uint32_t)(br * ROWB + bhf * 32);
        *reinterpret_cast<uint4*>(smem + d)      = make_uint4(h[0], h[1], h[2], h[3]);
        *reinterpret_cast<uint4*>(smem + d + 16) = make_uint4(h[4], h[5], h[6], h[7]);
    };
    auto issueA = [&](int it) {
        uint32_t ring = sb + (uint32_t)(it & 1) * (2 * ATILE2);
        int kk = it * 32;
#pragma unroll
        for (int i = 0; i < 4; i++) {
            int idx = t + i * 256;
            int row = idx >> 2, col = idx & 3;
            uint32_t so = (uint32_t)(row * ROWB + col * 16);
            const size_t ga = (size_t)row * K + kk + col * 8;
            cp_async16(ring + so, Ah + ga);
            cp_async16(ring + ATILE2 + so, Al + ga);
        }
        cp_commit();
    };

    const int a_row = (lane & 15);
    const int a_kof = ((lane >> 4) & 1) * 16;
    const int b_row = ((lane >> 4) << 3) + (lane & 7);
    const int b_kof = ((lane >> 3) & 1) * 16;
    const int g = lane >> 2, q = lane & 3;

    issueA(0); issueA(1);
    ldgB(0);
    cp_wait<1>();          // A(0) done
    stsB(0);
    __syncthreads();

    for (int it = 0; it < KT; ++it) {
        if (it + 1 < KT) ldgB(it + 1);

        const uint32_t ring = sb + (uint32_t)(it & 1) * (2 * ATILE2);
        const uint32_t bT = SG_BOFF + (uint32_t)(it & 1) * HTILE;
#pragma unroll
        for (int ks = 0; ks < 2; ks++) {
            const int kb = ks * 32;
            uint32_t bh[8][2];
#pragma unroll
            for (int njp = 0; njp < 4; njp++) {
                uint32_t addr = sb + bT + (wn * 64 + njp * 16 + b_row) * ROWB + kb + b_kof;
                uint32_t q0, q1, q2, q3;
                ldmx4(q0, q1, q2, q3, addr);
                bh[njp * 2][0] = q0; bh[njp * 2][1] = q1;
                bh[njp * 2 + 1][0] = q2; bh[njp * 2 + 1][1] = q3;
            }
#pragma unroll
            for (int mi = 0; mi < 4; mi++) {
                const uint32_t aro = (wm * 64 + mi * 16 + a_row) * ROWB + kb + a_kof;
                uint32_t ah[4], al[4];
                ldmx4(ah[0], ah[1], ah[2], ah[3], ring + aro);
                ldmx4(al[0], al[1], al[2], al[3], ring + ATILE2 + aro);
#pragma unroll
                for (int nj = 0; nj < 8; nj++) mma16816(acc[mi][nj], ah, bh[nj]);
#pragma unroll
                for (int nj = 0; nj < 8; nj++) mma16816(acc[mi][nj], al, bh[nj]);
            }
        }
        if (it + 1 < KT) {
            cp_wait<0>();          // A(it+1) done (issued >=1 iter ago)
            stsB((it + 1) & 1);
        }
        __syncthreads();
        if (it + 2 < KT) issueA(it + 2);
    }

    // epilogue: store C + softmax partials
    float pm[8], ps[8];
#pragma unroll
    for (int mi = 0; mi < 4; mi++) {
        float m0v = -1e30f, s0v = 0.f, m1v = -1e30f, s1v = 0.f;
        int row0 = wm * 64 + mi * 16 + g;
        int row1 = row0 + 8;
#pragma unroll
        for (int nj = 0; nj < 8; nj++) {
            int col = n0 + wn * 64 + nj * 8 + 2 * q;
            float b0 = bias[col], b1 = bias[col + 1];
            float v00 = acc[mi][nj][0] + b0, v01 = acc[mi][nj][1] + b1;
            float v10 = acc[mi][nj][2] + b0, v11 = acc[mi][nj][3] + b1;
            *reinterpret_cast<float2*>(&C[(size_t)row0 * N + col]) = make_float2(v00, v01);
            *reinterpret_cast<float2*>(&C[(size_t)row1 * N + col]) = make_float2(v10, v11);
            msum(m0v, s0v, v00, 1.f); msum(m0v, s0v, v01, 1.f);
            msum(m1v, s1v, v10, 1.f); msum(m1v, s1v, v11, 1.f);
        }
#pragma unroll
        for (int off = 1; off <= 2; off <<= 1) {
            float om = __shfl_xor_sync(0xffffffffu, m0v, off);
            float os = __shfl_xor_sync(0xffffffffu, s0v, off);
            msum(m0v, s0v, om, os);
            om = __shfl_xor_sync(0xffffffffu, m1v, off);
            os = __shfl_xor_sync(0xffffffffu, s1v, off);
            msum(m1v, s1v, om, os);
        }
        pm[mi * 2] = m0v; ps[mi * 2] = s0v;
        pm[mi * 2 + 1] = m1v; ps[mi * 2 + 1] = s1v;
    }
    __syncthreads();
    float* s_pm = reinterpret_cast<float*>(smem);
    float* s_ps = reinterpret_cast<float*>(smem + 1024);
    if (wn == 0 && q == 0) {
#pragma unroll
        for (int i = 0; i < 8; i++) {
            int r_in = wm * 64 + (i >> 1) * 16 + g + (i & 1) * 8;
            s_pm[r_in] = pm[i]; s_ps[r_in] = ps[i];
        }
    }
    __syncthreads();
    if (wn == 1 && q == 0) {
#pragma unroll
        for (int i = 0; i < 8; i++) {
            int r_in = wm * 64 + (i >> 1) * 16 + g + (i & 1) * 8;
            float m = pm[i], s = ps[i];
            msum(m, s, s_pm[r_in], s_ps[r_in]);
            g_pmax[(size_t)r_in * NX_ + bx] = m;
            g_psum[(size_t)r_in * NX_ + bx] = s;
        }
    }
}

__global__ void __launch_bounds__(256, 1)
mma_scores(const float* __restrict__ enc, const float* __restrict__ Wc_b,
           const float* __restrict__ Wo_w, const float* __restrict__ Wo_b,
           float* __restrict__ pred) {
    extern __shared__ __align__(16) char smem[];
    const int bid = blockIdx.x;
    if (bid < SC_CTAS) {
        sc_body(smem, bid & 3, bid >> 2, enc, g_wc_hi, Wc_b, g_hidden, g_sc);
    } else {
        sg_body(smem, bid - SC_CTAS, g_hid_hi, g_hid_lo, Wo_w, Wo_b, pred);
    }
}

// ---------------- GRU (+ hidden fp16 split) ----------------
__global__ void gru_kernel(const float* __restrict__ prev,
                           float* __restrict__ outHidden) {
    int idx = blockIdx.x * blockDim.x + threadIdx.x;
    int b = idx >> 9, h = idx & (H_ - 1);
    const float* gi = g_gi + (size_t)b * G_;
    const float* gh = g_gh + (size_t)b * G_;
    float ir = gi[h], iz = gi[h + H_], inn = gi[h + 2 * H_];
    float hr = gh[h], hz = gh[h + H_], hn = gh[h + 2 * H_];
    float r = 1.f / (1.f + expf(-(ir + hr)));
    float z = 1.f / (1.f + expf(-(iz + hz)));
    float n = tanhf(inn + r * hn);
    float hv = (1.f - z) * n + z * prev[idx];
    g_hidden[idx] = hv;
    outHidden[idx] = hv;
    __half hb = __float2half_rn(hv);
    g_hid_hi[idx] = hb;
    g_hid_lo[idx] = __float2half_rn(hv - __half2float(hb));
}

// ---------------- softmax ----------------
__global__ void __launch_bounds__(512)
softmax_kernel(float* __restrict__ pred, const int* __restrict__ src,
               const int* __restrict__ ids) {
    __shared__ float s_lc[S_];
    __shared__ float s_m[512];
    __shared__ float s_s[512];
    __shared__ int s_cnt;
    const int b = blockIdx.x, t = threadIdx.x;
    float* row = pred + (size_t)b * V_;

    if (t == 0) s_cnt = 0;
    if (t < S_) {
        float mask = (src[b * S_ + t] == 0) ? -1000.f : 0.f;
        s_lc[t] = tanhf(g_sc[b * S_ + t] + mask);
    }
    __syncthreads();

    float m = -1e30f, s = 0.f;
    for (int x = t; x < NX_; x += 512)
        msum(m, s, g_pmax[(size_t)b * NX_ + x], g_psum[(size_t)b * NX_ + x]);
    if (t < S_) msum(m, s, s_lc[t], 1.f);
    s_m[t] = m; s_s[t] = s;
    __syncthreads();
    for (int o = 256; o; o >>= 1) {
        if (t < o) {
            float mm = s_m[t], ss = s_s[t];
            msum(mm, ss, s_m[t + o], s_s[t + o]);
            s_m[t] = mm; s_s[t] = ss;
        }
        __syncthreads();
    }
    float gmax = s_m[0];
    float inv = 1.f / s_s[0];

    for (int v = t; v < V_; v += 512) row[v] = __expf(row[v] - gmax) * inv;

    int id = ids[b];
    if (t < S_ && src[b * S_ + t] == id) atomicAdd(&s_cnt, 1);
    __syncthreads();

    if (t < S_) {
        float pc = __expf(s_lc[t] - gmax) * inv;
        atomicAdd(&row[src[b * S_ + t]], pc);
        float eq = (src[b * S_ + t] == id) ? 1.f : 0.f;
        g_attn[b * S_ + t] = pc * eq / fmaxf((float)s_cnt, 1.f);
    }
}

__global__ void __launch_bounds__(256)
weighted_kernel(const float* __restrict__ enc, float* __restrict__ outW) {
    __shared__ float s_a[S_];
    const int b = blockIdx.x, t = threadIdx.x;
    if (t < S_) s_a[t] = g_attn[b * S_ + t];
    __syncthreads();
    float4 acc = make_float4(0.f, 0.f, 0.f, 0.f);
    const float4* e4 = reinterpret_cast<const float4*>(enc + (size_t)b * S_ * (2 * H_));
    for (int s = 0; s < S_; s++) {
        float w = s_a[s];
        if (w != 0.f) {
            float4 e = e4[s * 256 + t];
            acc.x = fmaf(w, e.x, acc.x); acc.y = fmaf(w, e.y, acc.y);
            acc.z = fmaf(w, e.z, acc.z); acc.w = fmaf(w, e.w, acc.w);
        }
    }
    reinterpret_cast<float4*>(outW)[b * 256 + t] = acc;
}

// ---------------- launch ----------------
extern "C" void kernel_launch(void* const* d_in, const int* in_sizes, int n_in,
                              void* d_out, int out_size) {
    const int*   input_ids = (const int*)d_in[0];
    const float* encoded   = (const float*)d_in[1];
    const int*   src       = (const int*)d_in[2];
    const float* prev      = (const float*)d_in[3];
    const float* weighted  = (const float*)d_in[4];
    const float* embed_w   = (const float*)d_in[6];
    const float* w_ih      = (const float*)d_in[7];
    const float* w_hh      = (const float*)d_in[8];
    const float* b_ih      = (const float*)d_in[9];
    const float* b_hh      = (const float*)d_in[10];
    const float* Wo_w      = (const float*)d_in[13];
    const float* Wo_b      = (const float*)d_in[14];
    const float* Wc_w      = (const float*)d_in[15];
    const float* Wc_b      = (const float*)d_in[16];

    float* pred        = (float*)d_out;
    float* outHidden   = pred + (size_t)B_ * V_;
    float* outWeighted = outHidden + (size_t)B_ * H_;

    cudaFuncSetAttribute(mma_gates, cudaFuncAttributeMaxDynamicSharedMemorySize, GATES_SMEM);
    cudaFuncSetAttribute(mma_scores, cudaFuncAttributeMaxDynamicSharedMemorySize, SCORES_SMEM);

    prep_kernel<<<PREP_CTAS, 256>>>(input_ids, embed_w, weighted, prev,
                                    w_ih, w_hh, Wc_w);

    mma_gates<<<dim3(G_ / 128, B_ / 128, 4), 256, GATES_SMEM>>>(b_ih, b_hh);

    gru_kernel<<<(B_ * H_) / 256, 256>>>(prev, outHidden);

    mma_scores<<<SC_CTAS + SG_CTAS, 256, SCORES_SMEM>>>(
        encoded, Wc_b, Wo_w, Wo_b, pred);

    softmax_kernel<<<B_, 512>>>(pred, src, input_ids);

    weighted_kernel<<<B_, 256>>>(encoded, outWeighted);

    (void)in_sizes; (void)n_in; (void)out_size;
}

// round 14
// speedup vs baseline: 1.4913x; 1.4913x over previous
#include <cuda_runtime.h>
#include <cuda_fp16.h>
#include <math.h>
#include <stdint.h>

namespace {
constexpr int B_ = 256;
constexpr int S_ = 128;
constexpr int H_ = 512;
constexpr int E_ = 512;
constexpr int V_ = 32000;
constexpr int IN_ = E_ + 2 * H_;   // 1536
constexpr int G_ = 3 * H_;         // 1536
constexpr int NX_ = V_ / 128;      // 250
}

// ---------------- static scratch ----------------
__device__ float g_gi[B_ * G_];
__device__ float g_gh[B_ * G_];
__device__ float g_hidden[B_ * H_];
__device__ float g_sc[B_ * S_];
__device__ float g_attn[B_ * S_];
__device__ float g_pmax[B_ * NX_];
__device__ float g_psum[B_ * NX_];
__device__ __half g_x_hi[B_ * IN_];
__device__ __half g_x_lo[B_ * IN_];
__device__ __half g_prev_hi[B_ * H_];
__device__ __half g_prev_lo[B_ * H_];
__device__ __half g_wih_hi[G_ * IN_];
__device__ __half g_whh_hi[G_ * H_];
__device__ __half g_wc_hi[H_ * 2 * H_];
__device__ __half g_hid_hi[B_ * H_];

// ---------------- helpers ----------------
__device__ __forceinline__ void cp_async16(uint32_t s, const void* g) {
    asm volatile("cp.async.cg.shared.global [%0], [%1], 16;\n"
                 :: "r"(s), "l"(g) : "memory");
}
__device__ __forceinline__ void cp_commit() {
    asm volatile("cp.async.commit_group;\n" ::: "memory");
}
template <int N>
__device__ __forceinline__ void cp_wait() {
    asm volatile("cp.async.wait_group %0;\n" :: "n"(N) : "memory");
}
__device__ __forceinline__ uint32_t smem_u32(const void* p) {
    uint32_t a;
    asm("{ .reg .u64 t; cvta.to.shared.u64 t, %1; cvt.u32.u64 %0, t; }"
        : "=r"(a) : "l"(p));
    return a;
}
__device__ __forceinline__ void ldmx4(uint32_t& r0, uint32_t& r1, uint32_t& r2,
                                      uint32_t& r3, uint32_t addr) {
    asm volatile("ldmatrix.sync.aligned.m8n8.x4.shared.b16 {%0,%1,%2,%3}, [%4];\n"
                 : "=r"(r0), "=r"(r1), "=r"(r2), "=r"(r3) : "r"(addr));
}
__device__ __forceinline__ void mma16816(float* d, const uint32_t* a,
                                         const uint32_t* b) {
    asm volatile(
        "mma.sync.aligned.m16n8k16.row.col.f32.f16.f16.f32 "
        "{%0,%1,%2,%3}, {%4,%5,%6,%7}, {%8,%9}, {%0,%1,%2,%3};\n"
        : "+f"(d[0]), "+f"(d[1]), "+f"(d[2]), "+f"(d[3])
        : "r"(a[0]), "r"(a[1]), "r"(a[2]), "r"(a[3]), "r"(b[0]), "r"(b[1]));
}
__device__ __forceinline__ uint32_t f2h2(float2 f) {
    __half2 h = __float22half2_rn(f);
    return *reinterpret_cast<uint32_t*>(&h);
}
__device__ __forceinline__ void split2h(float2 f, uint32_t& hi, uint32_t& lo) {
    hi = f2h2(f);
    __half2 hh = *reinterpret_cast<__half2*>(&hi);
    float2 fh = __half22float2(hh);
    lo = f2h2(make_float2(f.x - fh.x, f.y - fh.y));
}
__device__ __forceinline__ uint2 h4_of(float4 v) {
    return make_uint2(f2h2(make_float2(v.x, v.y)), f2h2(make_float2(v.z, v.w)));
}
__device__ __forceinline__ void hl4_of(float4 v, uint2& h, uint2& l) {
    uint32_t h0, h1, l0, l1;
    split2h(make_float2(v.x, v.y), h0, l0);
    split2h(make_float2(v.z, v.w), h1, l1);
    h = make_uint2(h0, h1); l = make_uint2(l0, l1);
}
__device__ __forceinline__ void msum(float& m, float& s, float om, float os) {
    float nm = fmaxf(m, om);
    s = s * __expf(m - nm) + os * __expf(om - nm);
    m = nm;
}

// =====================================================================
// Fused prep
// =====================================================================
constexpr int PC0 = 96, PC1 = 32, PC2 = 576, PC3 = 192, PC4 = 512, PC5 = 96, PC6 = 8;
constexpr int PREP_CTAS = PC0 + PC1 + PC2 + PC3 + PC4 + PC5 + PC6;

__global__ void __launch_bounds__(256)
prep_kernel(const int* __restrict__ ids, const float* __restrict__ emb,
            const float* __restrict__ weighted, const float* __restrict__ prev,
            const float* __restrict__ w_ih, const float* __restrict__ w_hh,
            const float* __restrict__ Wc_w) {
    int bid = blockIdx.x;
    const int tid = threadIdx.x;
    if (bid < PC0) {
        const int n4 = B_ * IN_ / 4, T = PC0 * 256, J4 = IN_ / 4;
        for (int i = bid * 256 + tid; i < n4; i += T) {
            int b = i / J4, j = (i - b * J4) * 4;
            float4 v = (j < E_)
                ? *reinterpret_cast<const float4*>(emb + (size_t)ids[b] * E_ + j)
                : *reinterpret_cast<const float4*>(weighted + (size_t)b * 2 * H_ + (j - E_));
            uint2 h, l; hl4_of(v, h, l);
            *reinterpret_cast<uint2*>(g_x_hi + (size_t)i * 4) = h;
            *reinterpret_cast<uint2*>(g_x_lo + (size_t)i * 4) = l;
        }
        return;
    }
    bid -= PC0;
    if (bid < PC1) {
        const int n4 = B_ * H_ / 4, T = PC1 * 256;
        const float4* s4 = reinterpret_cast<const float4*>(prev);
        for (int i = bid * 256 + tid; i < n4; i += T) {
            uint2 h, l; hl4_of(s4[i], h, l);
            *reinterpret_cast<uint2*>(g_prev_hi + (size_t)i * 4) = h;
            *reinterpret_cast<uint2*>(g_prev_lo + (size_t)i * 4) = l;
        }
        return;
    }
    bid -= PC1;
    if (bid < PC2) {
        const int n4 = G_ * IN_ / 4, T = PC2 * 256;
        const float4* s4 = reinterpret_cast<const float4*>(w_ih);
        for (int i = bid * 256 + tid; i < n4; i += T)
            *reinterpret_cast<uint2*>(g_wih_hi + (size_t)i * 4) = h4_of(s4[i]);
        return;
    }
    bid -= PC2;
    if (bid < PC3) {
        const int n4 = G_ * H_ / 4, T = PC3 * 256;
        const float4* s4 = reinterpret_cast<const float4*>(w_hh);
        for (int i = bid * 256 + tid; i < n4; i += T)
            *reinterpret_cast<uint2*>(g_whh_hi + (size_t)i * 4) = h4_of(s4[i]);
        return;
    }
    bid -= PC3;
    if (bid < PC4) {
        const int n4 = H_ * 2 * H_ / 4, T = PC4 * 256;
        const float4* s4 = reinterpret_cast<const float4*>(Wc_w);
        for (int i = bid * 256 + tid; i < n4; i += T)
            *reinterpret_cast<uint2*>(g_wc_hi + (size_t)i * 4) = h4_of(s4[i]);
        return;
    }
    bid -= PC4;
    if (bid < PC5) {
        const int n4 = B_ * G_ / 4, T = PC5 * 256;
        float4* p = reinterpret_cast<float4*>(g_gi);
        for (int i = bid * 256 + tid; i < n4; i += T)
            p[i] = make_float4(0.f, 0.f, 0.f, 0.f);
        return;
    }
    bid -= PC5;
    {
        const int n4 = B_ * S_ / 4, T = PC6 * 256;
        float4* p = reinterpret_cast<float4*>(g_sc);
        for (int i = bid * 256 + tid; i < n4; i += T)
            p[i] = make_float4(0.f, 0.f, 0.f, 0.f);
    }
}

// ---------------- common GEMM constants ----------------
constexpr int ROWB = 80;
constexpr int HTILE = 128 * ROWB;          // 10240 B

// =====================================================================
// Gates: gi split-K z=0..2 + gh z=3 (unchanged)
// =====================================================================
constexpr int GATES_SMEM = 3 * 3 * HTILE;

__global__ void __launch_bounds__(256, 2)
mma_gates(const float* __restrict__ b_ih, const float* __restrict__ b_hh) {
    extern __shared__ __align__(16) char smem[];
    const int t = threadIdx.x;
    const int lane = t & 31;
    const int wid = t >> 5;
    const int wm = wid & 3, wn = wid >> 2;
    const int m0 = blockIdx.y * 128, n0 = blockIdx.x * 128;
    const int z = blockIdx.z;
    const uint32_t sb = smem_u32(smem);

    const __half *Ah, *Al, *Bh;
    const float* bias;
    float* C;
    int K, kstart;
    bool atomic, addBias;
    if (z < 3) {
        Ah = g_x_hi; Al = g_x_lo; Bh = g_wih_hi;
        bias = b_ih; C = g_gi; K = IN_; kstart = z * 512;
        atomic = true; addBias = (z == 0);
    } else {
        Ah = g_prev_hi; Al = g_prev_lo; Bh = g_whh_hi;
        bias = b_hh; C = g_gh; K = H_; kstart = 0;
        atomic = false; addBias = true;
    }
    const int KCH = 16;

    float acc[2][8][4];
#pragma unroll
    for (int i = 0; i < 2; i++)
#pragma unroll
        for (int j = 0; j < 8; j++)
#pragma unroll
            for (int r = 0; r < 4; r++) acc[i][j][r] = 0.f;

    auto issue = [&](int it) {
        uint32_t st = sb + (uint32_t)(it % 3) * (3 * HTILE);
        int kk = kstart + it * 32;
#pragma unroll
        for (int i = 0; i < 2; i++) {
            int idx = t + i * 256;
            int row = idx >> 2, col = idx & 3;
            uint32_t so = (uint32_t)(row * ROWB + col * 16);
            const size_t ga = (size_t)(m0 + row) * K + kk + col * 8;
            const size_t gb = (size_t)(n0 + row) * K + kk + col * 8;
            cp_async16(st + so, Ah + ga);
            cp_async16(st + HTILE + so, Al + ga);
            cp_async16(st + 2 * HTILE + so, Bh + gb);
        }
        cp_commit();
    };

    const int a_row = (lane & 15);
    const int a_kof = ((lane >> 4) & 1) * 16;
    const int b_row = ((lane >> 4) << 3) + (lane & 7);
    const int b_kof = ((lane >> 3) & 1) * 16;
    const int g = lane >> 2, q = lane & 3;

    issue(0); issue(1);
    for (int it = 0; it < KCH; ++it) {
        if (it + 1 < KCH) cp_wait<1>(); else cp_wait<0>();
        __syncthreads();
        if (it + 2 < KCH) issue(it + 2);
        const uint32_t st = sb + (uint32_t)(it % 3) * (3 * HTILE);
#pragma unroll
        for (int ks = 0; ks < 2; ks++) {
            const int kb = ks * 32;
            uint32_t bh[8][2];
#pragma unroll
            for (int njp = 0; njp < 4; njp++) {
                uint32_t addr = st + 2 * HTILE + (wn * 64 + njp * 16 + b_row) * ROWB + kb + b_kof;
                uint32_t q0, q1, q2, q3;
                ldmx4(q0, q1, q2, q3, addr);
                bh[njp * 2][0] = q0; bh[njp * 2][1] = q1;
                bh[njp * 2 + 1][0] = q2; bh[njp * 2 + 1][1] = q3;
            }
#pragma unroll
            for (int mi = 0; mi < 2; mi++) {
                const uint32_t aro = (wm * 32 + mi * 16 + a_row) * ROWB + kb + a_kof;
                uint32_t ah[4], al[4];
                ldmx4(ah[0], ah[1], ah[2], ah[3], st + aro);
                ldmx4(al[0], al[1], al[2], al[3], st + HTILE + aro);
#pragma unroll
                for (int nj = 0; nj < 8; nj++) mma16816(acc[mi][nj], ah, bh[nj]);
#pragma unroll
                for (int nj = 0; nj < 8; nj++) mma16816(acc[mi][nj], al, bh[nj]);
            }
        }
    }

#pragma unroll
    for (int mi = 0; mi < 2; mi++) {
        int row0 = m0 + wm * 32 + mi * 16 + g;
        int row1 = row0 + 8;
#pragma unroll
        for (int nj = 0; nj < 8; nj++) {
            int col = n0 + wn * 64 + nj * 8 + 2 * q;
            float b0 = addBias ? bias[col] : 0.f;
            float b1 = addBias ? bias[col + 1] : 0.f;
            if (atomic) {
                atomicAdd(&C[(size_t)row0 * G_ + col],     acc[mi][nj][0] + b0);
                atomicAdd(&C[(size_t)row0 * G_ + col + 1], acc[mi][nj][1] + b1);
                atomicAdd(&C[(size_t)row1 * G_ + col],     acc[mi][nj][2] + b0);
                atomicAdd(&C[(size_t)row1 * G_ + col + 1], acc[mi][nj][3] + b1);
            } else {
                float2 o0 = make_float2(acc[mi][nj][0] + b0, acc[mi][nj][1] + b1);
                float2 o1 = make_float2(acc[mi][nj][2] + b0, acc[mi][nj][3] + b1);
                *reinterpret_cast<float2*>(&C[(size_t)row0 * G_ + col]) = o0;
                *reinterpret_cast<float2*>(&C[(size_t)row1 * G_ + col]) = o1;
            }
        }
    }
}

// =====================================================================
// Merged scores kernel (R12 shape: CTA 128x128, warp 32x64, 2 CTA/SM).
// blocks [0, 1024) -> score_c; [1024, 1524) -> score_g (now 1-PASS).
// =====================================================================
constexpr uint32_t SG_B = 3 * HTILE;            // A ring: 3 stages x 1 tile
constexpr int SG_SMEM = SG_B + 2 * HTILE;       // 51200
constexpr uint32_t SC_B = 2 * HTILE;
constexpr int SC_SMEM = SC_B + 3 * HTILE;       // 51200
constexpr int SCORES_SMEM = 51200;
constexpr int SC_CTAS = 4 * 256;                // 1024
constexpr int SG_CTAS = NX_ * 2;                // 500

__device__ void sg_body(char* smem, int bx, int by,
                        const __half* __restrict__ Ah,
                        const float* __restrict__ Bf, const float* __restrict__ bias,
                        float* __restrict__ C) {
    const int K = H_, N = V_;
    const int t = threadIdx.x;
    const int lane = t & 31;
    const int wid = t >> 5;
    const int wm = wid & 3, wn = wid >> 2;
    const int m0 = by * 128, n0 = bx * 128;
    const uint32_t sb = smem_u32(smem);

    float acc[2][8][4];
#pragma unroll
    for (int i = 0; i < 2; i++)
#pragma unroll
        for (int j = 0; j < 8; j++)
#pragma unroll
            for (int r = 0; r < 4; r++) acc[i][j][r] = 0.f;

    const int KT = K / 32;   // 16
    const int br = t >> 1, bhf = t & 1;
    const float* Bbase = Bf + (size_t)(n0 + br) * K + bhf * 16;

    float4 r4[4];
    auto ldgB = [&](int it) {
        const float* p = Bbase + it * 32;
#pragma unroll
        for (int i = 0; i < 4; i++) r4[i] = *reinterpret_cast<const float4*>(p + i * 4);
    };
    auto stsB = [&](int buf) {
        uint32_t h[8];
#pragma unroll
        for (int i = 0; i < 4; i++) {
            h[i * 2]     = f2h2(make_float2(r4[i].x, r4[i].y));
            h[i * 2 + 1] = f2h2(make_float2(r4[i].z, r4[i].w));
        }
        uint32_t d = SG_B + (uint32_t)buf * HTILE + (uint32_t)(br * ROWB + bhf * 32);
        *reinterpret_cast<uint4*>(smem + d)      = make_uint4(h[0], h[1], h[2], h[3]);
        *reinterpret_cast<uint4*>(smem + d + 16) = make_uint4(h[4], h[5], h[6], h[7]);
    };
    auto issueA = [&](int it) {
        uint32_t ring = sb + (uint32_t)(it % 3) * HTILE;
        int kk = it * 32;
#pragma unroll
        for (int i = 0; i < 2; i++) {
            int idx = t + i * 256;
            int row = idx >> 2, col = idx & 3;
            uint32_t so = (uint32_t)(row * ROWB + col * 16);
            cp_async16(ring + so, Ah + (size_t)(m0 + row) * K + kk + col * 8);
        }
        cp_commit();
    };

    const int a_row = (lane & 15);
    const int a_kof = ((lane >> 4) & 1) * 16;
    const int b_row = ((lane >> 4) << 3) + (lane & 7);
    const int b_kof = ((lane >> 3) & 1) * 16;
    const int g = lane >> 2, q = lane & 3;

    issueA(0); issueA(1);
    ldgB(0);
    cp_wait<1>();
    stsB(0);
    __syncthreads();

    for (int it = 0; it < KT; ++it) {
        if (it + 1 < KT) ldgB(it + 1);
        if (it + 2 < KT) issueA(it + 2);

        const uint32_t ring = sb + (uint32_t)(it % 3) * HTILE;
        const uint32_t bT = SG_B + (uint32_t)(it & 1) * HTILE;
#pragma unroll
        for (int ks = 0; ks < 2; ks++) {
            const int kb = ks * 32;
            uint32_t bh[8][2];
#pragma unroll
            for (int njp = 0; njp < 4; njp++) {
                uint32_t addr = sb + bT + (wn * 64 + njp * 16 + b_row) * ROWB + kb + b_kof;
                uint32_t q0, q1, q2, q3;
                ldmx4(q0, q1, q2, q3, addr);
                bh[njp * 2][0] = q0; bh[njp * 2][1] = q1;
                bh[njp * 2 + 1][0] = q2; bh[njp * 2 + 1][1] = q3;
            }
#pragma unroll
            for (int mi = 0; mi < 2; mi++) {
                const uint32_t aro = (wm * 32 + mi * 16 + a_row) * ROWB + kb + a_kof;
                uint32_t ah[4];
                ldmx4(ah[0], ah[1], ah[2], ah[3], ring + aro);
#pragma unroll
                for (int nj = 0; nj < 8; nj++) mma16816(acc[mi][nj], ah, bh[nj]);
            }
        }
        if (it + 1 < KT) {
            if (it + 2 < KT) cp_wait<1>(); else cp_wait<0>();
            stsB((it + 1) & 1);
        }
        __syncthreads();
    }

    float pm[4], ps[4];
#pragma unroll
    for (int mi = 0; mi < 2; mi++) {
        float m0v = -1e30f, s0v = 0.f, m1v = -1e30f, s1v = 0.f;
        int row0 = m0 + wm * 32 + mi * 16 + g;
        int row1 = row0 + 8;
#pragma unroll
        for (int nj = 0; nj < 8; nj++) {
            int col = n0 + wn * 64 + nj * 8 + 2 * q;
            float b0 = bias[col], b1 = bias[col + 1];
            float v00 = acc[mi][nj][0] + b0, v01 = acc[mi][nj][1] + b1;
            float v10 = acc[mi][nj][2] + b0, v11 = acc[mi][nj][3] + b1;
            *reinterpret_cast<float2*>(&C[(size_t)row0 * N + col]) = make_float2(v00, v01);
            *reinterpret_cast<float2*>(&C[(size_t)row1 * N + col]) = make_float2(v10, v11);
            msum(m0v, s0v, v00, 1.f); msum(m0v, s0v, v01, 1.f);
            msum(m1v, s1v, v10, 1.f); msum(m1v, s1v, v11, 1.f);
        }
#pragma unroll
        for (int off = 1; off <= 2; off <<= 1) {
            float om = __shfl_xor_sync(0xffffffffu, m0v, off);
            float os = __shfl_xor_sync(0xffffffffu, s0v, off);
            msum(m0v, s0v, om, os);
            om = __shfl_xor_sync(0xffffffffu, m1v, off);
            os = __shfl_xor_sync(0xffffffffu, s1v, off);
            msum(m1v, s1v, om, os);
        }
        pm[mi * 2] = m0v; ps[mi * 2] = s0v;
        pm[mi * 2 + 1] = m1v; ps[mi * 2 + 1] = s1v;
    }
    __syncthreads();
    float* s_pm = reinterpret_cast<float*>(smem);
    float* s_ps = reinterpret_cast<float*>(smem + 512);
    if (wn == 0 && q == 0) {
#pragma unroll
        for (int i = 0; i < 4; i++) {
            int r_in = wm * 32 + (i >> 1) * 16 + g + (i & 1) * 8;
            s_pm[r_in] = pm[i]; s_ps[r_in] = ps[i];
        }
    }
    __syncthreads();
    if (wn == 1 && q == 0) {
#pragma unroll
        for (int i = 0; i < 4; i++) {
            int r_in = wm * 32 + (i >> 1) * 16 + g + (i & 1) * 8;
            float m = pm[i], s = ps[i];
            msum(m, s, s_pm[r_in], s_ps[r_in]);
            g_pmax[(size_t)(m0 + r_in) * NX_ + bx] = m;
            g_psum[(size_t)(m0 + r_in) * NX_ + bx] = s;
        }
    }
}

__device__ void sc_body(char* smem, int bx, int by,
                        const float* __restrict__ Af, const __half* __restrict__ Bh16,
                        const float* __restrict__ bias,
                        const float* __restrict__ hidden, float* __restrict__ scOut) {
    const int K = 2 * H_;
    const int t = threadIdx.x;
    const int lane = t & 31;
    const int wid = t >> 5;
    const int wm = wid & 3, wn = wid >> 2;
    const int m0 = by * 128, n0 = bx * 128;
    const uint32_t sb = smem_u32(smem);

    float acc[2][8][4];
#pragma unroll
    for (int i = 0; i < 2; i++)
#pragma unroll
        for (int j = 0; j < 8; j++)
#pragma unroll
            for (int r = 0; r < 4; r++) acc[i][j][r] = 0.f;

    const int KT = K / 32;   // 32
    const int ar = t >> 1, ahf = t & 1;
    const float* Abase = Af + (size_t)(m0 + ar) * K + ahf * 16;

    float4 r4[4];
    auto ldgA = [&](int it) {
        const float* p = Abase + it * 32;
#pragma unroll
        for (int i = 0; i < 4; i++) r4[i] = *reinterpret_cast<const float4*>(p + i * 4);
    };
    auto stsA = [&](int buf) {
        uint32_t h[8];
#pragma unroll
        for (int i = 0; i < 4; i++) {
            h[i * 2]     = f2h2(make_float2(r4[i].x, r4[i].y));
            h[i * 2 + 1] = f2h2(make_float2(r4[i].z, r4[i].w));
        }
        uint32_t d = (uint32_t)buf * HTILE + (uint32_t)(ar * ROWB + ahf * 32);
        *reinterpret_cast<uint4*>(smem + d)      = make_uint4(h[0], h[1], h[2], h[3]);
        *reinterpret_cast<uint4*>(smem + d + 16) = make_uint4(h[4], h[5], h[6], h[7]);
    };
    auto issueB = [&](int it) {
        uint32_t bt = sb + SC_B + (uint32_t)(it % 3) * HTILE;
        int kk = it * 32;
#pragma unroll
        for (int i = 0; i < 2; i++) {
            int idx = t + i * 256;
            int row = idx >> 2, col = idx & 3;
            cp_async16(bt + (uint32_t)(row * ROWB + col * 16),
                       Bh16 + (size_t)(n0 + row) * K + kk + col * 8);
        }
        cp_commit();
    };

    const int a_row = (lane & 15);
    const int a_kof = ((lane >> 4) & 1) * 16;
    const int b_row = ((lane >> 4) << 3) + (lane & 7);
    const int b_kof = ((lane >> 3) & 1) * 16;
    const int g = lane >> 2, q = lane & 3;

    issueB(0); issueB(1);
    ldgA(0);
    cp_wait<1>();
    stsA(0);
    __syncthreads();

    for (int it = 0; it < KT; ++it) {
        if (it + 1 < KT) ldgA(it + 1);
        if (it + 2 < KT) issueB(it + 2);

        const uint32_t aT = sb + (uint32_t)(it & 1) * HTILE;
        const uint32_t bT = sb + SC_B + (uint32_t)(it % 3) * HTILE;
#pragma unroll
        for (int ks = 0; ks < 2; ks++) {
            const int kb = ks * 32;
            uint32_t bh[8][2];
#pragma unroll
            for (int njp = 0; njp < 4; njp++) {
                uint32_t addr = bT + (wn * 64 + njp * 16 + b_row) * ROWB + kb + b_kof;
                uint32_t q0, q1, q2, q3;
                ldmx4(q0, q1, q2, q3, addr);
                bh[njp * 2][0] = q0; bh[njp * 2][1] = q1;
                bh[njp * 2 + 1][0] = q2; bh[njp * 2 + 1][1] = q3;
            }
#pragma unroll
            for (int mi = 0; mi < 2; mi++) {
                const uint32_t aro = (wm * 32 + mi * 16 + a_row) * ROWB + kb + a_kof;
                uint32_t ah[4];
                ldmx4(ah[0], ah[1], ah[2], ah[3], aT + aro);
#pragma unroll
                for (int nj = 0; nj < 8; nj++) mma16816(acc[mi][nj], ah, bh[nj]);
            }
        }
        if (it + 1 < KT) {
            if (it + 2 < KT) cp_wait<1>(); else cp_wait<0>();
            stsA((it + 1) & 1);
        }
        __syncthreads();
    }

    const int b = m0 >> 7;
#pragma unroll
    for (int mi = 0; mi < 2; mi++) {
        float p0 = 0.f, p1 = 0.f;
#pragma unroll
        for (int nj = 0; nj < 8; nj++) {
            int col = n0 + wn * 64 + nj * 8 + 2 * q;
            float bz0 = bias[col], bz1 = bias[col + 1];
            float hv0 = hidden[b * H_ + col], hv1 = hidden[b * H_ + col + 1];
            p0 = fmaf(tanhf(acc[mi][nj][0] + bz0), hv0, p0);
            p0 = fmaf(tanhf(acc[mi][nj][1] + bz1), hv1, p0);
            p1 = fmaf(tanhf(acc[mi][nj][2] + bz0), hv0, p1);
            p1 = fmaf(tanhf(acc[mi][nj][3] + bz1), hv1, p1);
        }
        p0 += __shfl_xor_sync(0xffffffffu, p0, 1);
        p0 += __shfl_xor_sync(0xffffffffu, p0, 2);
        p1 += __shfl_xor_sync(0xffffffffu, p1, 1);
        p1 += __shfl_xor_sync(0xffffffffu, p1, 2);
        if (q == 0) {
            int row = m0 + wm * 32 + mi * 16 + g;
            atomicAdd(&scOut[row], p0);
            atomicAdd(&scOut[row + 8], p1);
        }
    }
}

__global__ void __launch_bounds__(256, 2)
mma_scores(const float* __restrict__ enc, const float* __restrict__ Wc_b,
           const float* __restrict__ Wo_w, const float* __restrict__ Wo_b,
           float* __restrict__ pred) {
    extern __shared__ __align__(16) char smem[];
    const int bid = blockIdx.x;
    if (bid < SC_CTAS) {
        sc_body(smem, bid & 3, bid >> 2, enc, g_wc_hi, Wc_b, g_hidden, g_sc);
    } else {
        int id = bid - SC_CTAS;
        sg_body(smem, id % NX_, id / NX_, g_hid_hi, Wo_w, Wo_b, pred);
    }
}

// ---------------- GRU (+ hidden fp16 hi) ----------------
__global__ void gru_kernel(const float* __restrict__ prev,
                           float* __restrict__ outHidden) {
    int idx = blockIdx.x * blockDim.x + threadIdx.x;
    int b = idx >> 9, h = idx & (H_ - 1);
    const float* gi = g_gi + (size_t)b * G_;
    const float* gh = g_gh + (size_t)b * G_;
    float ir = gi[h], iz = gi[h + H_], inn = gi[h + 2 * H_];
    float hr = gh[h], hz = gh[h + H_], hn = gh[h + 2 * H_];
    float r = 1.f / (1.f + expf(-(ir + hr)));
    float z = 1.f / (1.f + expf(-(iz + hz)));
    float n = tanhf(inn + r * hn);
    float hv = (1.f - z) * n + z * prev[idx];
    g_hidden[idx] = hv;
    outHidden[idx] = hv;
    g_hid_hi[idx] = __float2half_rn(hv);
}

// ---------------- softmax ----------------
__global__ void __launch_bounds__(512)
softmax_kernel(float* __restrict__ pred, const int* __restrict__ src,
               const int* __restrict__ ids) {
    __shared__ float s_lc[S_];
    __shared__ float s_m[512];
    __shared__ float s_s[512];
    __shared__ int s_cnt;
    const int b = blockIdx.x, t = threadIdx.x;
    float* row = pred + (size_t)b * V_;

    if (t == 0) s_cnt = 0;
    if (t < S_) {
        float mask = (src[b * S_ + t] == 0) ? -1000.f : 0.f;
        s_lc[t] = tanhf(g_sc[b * S_ + t] + mask);
    }
    __syncthreads();

    float m = -1e30f, s = 0.f;
    for (int x = t; x < NX_; x += 512)
        msum(m, s, g_pmax[(size_t)b * NX_ + x], g_psum[(size_t)b * NX_ + x]);
    if (t < S_) msum(m, s, s_lc[t], 1.f);
    s_m[t] = m; s_s[t] = s;
    __syncthreads();
    for (int o = 256; o; o >>= 1) {
        if (t < o) {
            float mm = s_m[t], ss = s_s[t];
            msum(mm, ss, s_m[t + o], s_s[t + o]);
            s_m[t] = mm; s_s[t] = ss;
        }
        __syncthreads();
    }
    float gmax = s_m[0];
    float inv = 1.f / s_s[0];

    for (int v = t; v < V_; v += 512) row[v] = __expf(row[v] - gmax) * inv;

    int id = ids[b];
    if (t < S_ && src[b * S_ + t] == id) atomicAdd(&s_cnt, 1);
    __syncthreads();

    if (t < S_) {
        float pc = __expf(s_lc[t] - gmax) * inv;
        atomicAdd(&row[src[b * S_ + t]], pc);
        float eq = (src[b * S_ + t] == id) ? 1.f : 0.f;
        g_attn[b * S_ + t] = pc * eq / fmaxf((float)s_cnt, 1.f);
    }
}

__global__ void __launch_bounds__(256)
weighted_kernel(const float* __restrict__ enc, float* __restrict__ outW) {
    __shared__ float s_a[S_];
    const int b = blockIdx.x, t = threadIdx.x;
    if (t < S_) s_a[t] = g_attn[b * S_ + t];
    __syncthreads();
    float4 acc = make_float4(0.f, 0.f, 0.f, 0.f);
    const float4* e4 = reinterpret_cast<const float4*>(enc + (size_t)b * S_ * (2 * H_));
    for (int s = 0; s < S_; s++) {
        float w = s_a[s];
        if (w != 0.f) {
            float4 e = e4[s * 256 + t];
            acc.x = fmaf(w, e.x, acc.x); acc.y = fmaf(w, e.y, acc.y);
            acc.z = fmaf(w, e.z, acc.z); acc.w = fmaf(w, e.w, acc.w);
        }
    }
    reinterpret_cast<float4*>(outW)[b * 256 + t] = acc;
}

// ---------------- launch ----------------
extern "C" void kernel_launch(void* const* d_in, const int* in_sizes, int n_in,
                              void* d_out, int out_size) {
    const int*   input_ids = (const int*)d_in[0];
    const float* encoded   = (const float*)d_in[1];
    const int*   src       = (const int*)d_in[2];
    const float* prev      = (const float*)d_in[3];
    const float* weighted  = (const float*)d_in[4];
    const float* embed_w   = (const float*)d_in[6];
    const float* w_ih      = (const float*)d_in[7];
    const float* w_hh      = (const float*)d_in[8];
    const float* b_ih      = (const float*)d_in[9];
    const float* b_hh      = (const float*)d_in[10];
    const float* Wo_w      = (const float*)d_in[13];
    const float* Wo_b      = (const float*)d_in[14];
    const float* Wc_w      = (const float*)d_in[15];
    const float* Wc_b      = (const float*)d_in[16];

    float* pred        = (float*)d_out;
    float* outHidden   = pred + (size_t)B_ * V_;
    float* outWeighted = outHidden + (size_t)B_ * H_;

    cudaFuncSetAttribute(mma_gates, cudaFuncAttributeMaxDynamicSharedMemorySize, GATES_SMEM);
    cudaFuncSetAttribute(mma_scores, cudaFuncAttributeMaxDynamicSharedMemorySize, SCORES_SMEM);

    prep_kernel<<<PREP_CTAS, 256>>>(input_ids, embed_w, weighted, prev,
                                    w_ih, w_hh, Wc_w);

    mma_gates<<<dim3(G_ / 128, B_ / 128, 4), 256, GATES_SMEM>>>(b_ih, b_hh);

    gru_kernel<<<(B_ * H_) / 256, 256>>>(prev, outHidden);

    mma_scores<<<SC_CTAS + SG_CTAS, 256, SCORES_SMEM>>>(
        encoded, Wc_b, Wo_w, Wo_b, pred);

    softmax_kernel<<<B_, 512>>>(pred, src, input_ids);

    weighted_kernel<<<B_, 256>>>(encoded, outWeighted);

    (void)in_sizes; (void)n_in; (void)out_size;
}

// round 15
// speedup vs baseline: 1.5704x; 1.0531x over previous
#include <cuda_runtime.h>
#include <cuda_fp16.h>
#include <math.h>
#include <stdint.h>

namespace {
constexpr int B_ = 256;
constexpr int S_ = 128;
constexpr int H_ = 512;
constexpr int E_ = 512;
constexpr int V_ = 32000;
constexpr int IN_ = E_ + 2 * H_;   // 1536
constexpr int G_ = 3 * H_;         // 1536
constexpr int NX_ = V_ / 128;      // 250
}

// ---------------- static scratch ----------------
__device__ float g_gi[B_ * G_];
__device__ float g_gh[B_ * G_];
__device__ float g_hidden[B_ * H_];
__device__ float g_sc[B_ * S_];
__device__ float g_attn[B_ * S_];
__device__ float g_pmax[B_ * NX_];
__device__ float g_psum[B_ * NX_];
__device__ __half g_x_hi[B_ * IN_];
__device__ __half g_x_lo[B_ * IN_];
__device__ __half g_prev_hi[B_ * H_];
__device__ __half g_prev_lo[B_ * H_];
__device__ __half g_wc_hi[H_ * 2 * H_];
__device__ __half g_enc_hi[B_ * S_ * 2 * H_];
__device__ __half g_hid_hi[B_ * H_];

// ---------------- helpers ----------------
__device__ __forceinline__ void cp_async16(uint32_t s, const void* g) {
    asm volatile("cp.async.cg.shared.global [%0], [%1], 16;\n"
                 :: "r"(s), "l"(g) : "memory");
}
__device__ __forceinline__ void cp_commit() {
    asm volatile("cp.async.commit_group;\n" ::: "memory");
}
template <int N>
__device__ __forceinline__ void cp_wait() {
    asm volatile("cp.async.wait_group %0;\n" :: "n"(N) : "memory");
}
__device__ __forceinline__ uint32_t smem_u32(const void* p) {
    uint32_t a;
    asm("{ .reg .u64 t; cvta.to.shared.u64 t, %1; cvt.u32.u64 %0, t; }"
        : "=r"(a) : "l"(p));
    return a;
}
__device__ __forceinline__ void ldmx4(uint32_t& r0, uint32_t& r1, uint32_t& r2,
                                      uint32_t& r3, uint32_t addr) {
    asm volatile("ldmatrix.sync.aligned.m8n8.x4.shared.b16 {%0,%1,%2,%3}, [%4];\n"
                 : "=r"(r0), "=r"(r1), "=r"(r2), "=r"(r3) : "r"(addr));
}
__device__ __forceinline__ void mma16816(float* d, const uint32_t* a,
                                         const uint32_t* b) {
    asm volatile(
        "mma.sync.aligned.m16n8k16.row.col.f32.f16.f16.f32 "
        "{%0,%1,%2,%3}, {%4,%5,%6,%7}, {%8,%9}, {%0,%1,%2,%3};\n"
        : "+f"(d[0]), "+f"(d[1]), "+f"(d[2]), "+f"(d[3])
        : "r"(a[0]), "r"(a[1]), "r"(a[2]), "r"(a[3]), "r"(b[0]), "r"(b[1]));
}
__device__ __forceinline__ uint32_t f2h2(float2 f) {
    __half2 h = __float22half2_rn(f);
    return *reinterpret_cast<uint32_t*>(&h);
}
__device__ __forceinline__ void split2h(float2 f, uint32_t& hi, uint32_t& lo) {
    hi = f2h2(f);
    __half2 hh = *reinterpret_cast<__half2*>(&hi);
    float2 fh = __half22float2(hh);
    lo = f2h2(make_float2(f.x - fh.x, f.y - fh.y));
}
__device__ __forceinline__ uint2 h4_of(float4 v) {
    return make_uint2(f2h2(make_float2(v.x, v.y)), f2h2(make_float2(v.z, v.w)));
}
__device__ __forceinline__ void hl4_of(float4 v, uint2& h, uint2& l) {
    uint32_t h0, h1, l0, l1;
    split2h(make_float2(v.x, v.y), h0, l0);
    split2h(make_float2(v.z, v.w), h1, l1);
    h = make_uint2(h0, h1); l = make_uint2(l0, l1);
}
__device__ __forceinline__ void msum(float& m, float& s, float om, float os) {
    float nm = fmaxf(m, om);
    s = s * __expf(m - nm) + os * __expf(om - nm);
    m = nm;
}

// =====================================================================
// Fused prep: x split, prev split, Wc hi, zero gi, zero sc
// =====================================================================
constexpr int PC0 = 96, PC1 = 32, PC4 = 512, PC5 = 96, PC6 = 8;
constexpr int PREP_CTAS = PC0 + PC1 + PC4 + PC5 + PC6;   // 744

__global__ void __launch_bounds__(256)
prep_kernel(const int* __restrict__ ids, const float* __restrict__ emb,
            const float* __restrict__ weighted, const float* __restrict__ prev,
            const float* __restrict__ Wc_w) {
    int bid = blockIdx.x;
    const int tid = threadIdx.x;
    if (bid < PC0) {
        const int n4 = B_ * IN_ / 4, T = PC0 * 256, J4 = IN_ / 4;
        for (int i = bid * 256 + tid; i < n4; i += T) {
            int b = i / J4, j = (i - b * J4) * 4;
            float4 v = (j < E_)
                ? *reinterpret_cast<const float4*>(emb + (size_t)ids[b] * E_ + j)
                : *reinterpret_cast<const float4*>(weighted + (size_t)b * 2 * H_ + (j - E_));
            uint2 h, l; hl4_of(v, h, l);
            *reinterpret_cast<uint2*>(g_x_hi + (size_t)i * 4) = h;
            *reinterpret_cast<uint2*>(g_x_lo + (size_t)i * 4) = l;
        }
        return;
    }
    bid -= PC0;
    if (bid < PC1) {
        const int n4 = B_ * H_ / 4, T = PC1 * 256;
        const float4* s4 = reinterpret_cast<const float4*>(prev);
        for (int i = bid * 256 + tid; i < n4; i += T) {
            uint2 h, l; hl4_of(s4[i], h, l);
            *reinterpret_cast<uint2*>(g_prev_hi + (size_t)i * 4) = h;
            *reinterpret_cast<uint2*>(g_prev_lo + (size_t)i * 4) = l;
        }
        return;
    }
    bid -= PC1;
    if (bid < PC4) {
        const int n4 = H_ * 2 * H_ / 4, T = PC4 * 256;
        const float4* s4 = reinterpret_cast<const float4*>(Wc_w);
        for (int i = bid * 256 + tid; i < n4; i += T)
            *reinterpret_cast<uint2*>(g_wc_hi + (size_t)i * 4) = h4_of(s4[i]);
        return;
    }
    bid -= PC4;
    if (bid < PC5) {
        const int n4 = B_ * G_ / 4, T = PC5 * 256;
        float4* p = reinterpret_cast<float4*>(g_gi);
        for (int i = bid * 256 + tid; i < n4; i += T)
            p[i] = make_float4(0.f, 0.f, 0.f, 0.f);
        return;
    }
    bid -= PC5;
    {
        const int n4 = B_ * S_ / 4, T = PC6 * 256;
        float4* p = reinterpret_cast<float4*>(g_sc);
        for (int i = bid * 256 + tid; i < n4; i += T)
            p[i] = make_float4(0.f, 0.f, 0.f, 0.f);
    }
}

// ---------------- common GEMM constants ----------------
constexpr int ROWB = 80;
constexpr int HTILE = 128 * ROWB;          // 10240 B

// =====================================================================
// Gates + enc split in ONE launch.
// bid < 96: GEMM (z = bid/24: 0..2 gi split-K, 3 gh).
//   A: x/prev hi+lo pre-split fp16, cp.async 3-stage ring (2 tiles).
//   B: w_ih/w_hh fp32 LDG -> reg convert -> STS (2 bufs).
// bid >= 96: enc fp32 -> fp16 hi split (grid-stride).
// =====================================================================
constexpr int GATES_GEMM = 96;
constexpr int GATES_SPLIT = 512;
constexpr int GATES_CTAS = GATES_GEMM + GATES_SPLIT;
constexpr uint32_t GT_B = 3 * 2 * HTILE;        // 61440
constexpr int GATES_SMEM = GT_B + 2 * HTILE;    // 81920

__global__ void __launch_bounds__(256, 2)
mma_gates(const float* __restrict__ b_ih, const float* __restrict__ b_hh,
          const float* __restrict__ w_ih, const float* __restrict__ w_hh,
          const float* __restrict__ enc) {
    extern __shared__ __align__(16) char smem[];
    const int t = threadIdx.x;

    if (blockIdx.x >= GATES_GEMM) {
        // ---- enc split slice ----
        const int sbid = blockIdx.x - GATES_GEMM;
        const int n4 = B_ * S_ * 2 * H_ / 4;
        const int T = GATES_SPLIT * 256;
        const float4* s4 = reinterpret_cast<const float4*>(enc);
        uint2* h4 = reinterpret_cast<uint2*>(g_enc_hi);
        int i = sbid * 256 + t;
        for (; i + 3 * T < n4; i += 4 * T) {
            float4 v0 = s4[i], v1 = s4[i + T], v2 = s4[i + 2 * T], v3 = s4[i + 3 * T];
            h4[i] = h4_of(v0); h4[i + T] = h4_of(v1);
            h4[i + 2 * T] = h4_of(v2); h4[i + 3 * T] = h4_of(v3);
        }
        for (; i < n4; i += T) h4[i] = h4_of(s4[i]);
        return;
    }

    // ---- GEMM slice ----
    const int z = blockIdx.x / 24;
    const int rem = blockIdx.x % 24;
    const int by = rem / 12, bx = rem % 12;
    const int lane = t & 31;
    const int wid = t >> 5;
    const int wm = wid & 3, wn = wid >> 2;
    const int m0 = by * 128, n0 = bx * 128;
    const uint32_t sb = smem_u32(smem);

    const __half *Ah, *Al;
    const float *Bw, *bias;
    float* C;
    int K, kstart;
    bool atomic, addBias;
    if (z < 3) {
        Ah = g_x_hi; Al = g_x_lo; Bw = w_ih;
        bias = b_ih; C = g_gi; K = IN_; kstart = z * 512;
        atomic = true; addBias = (z == 0);
    } else {
        Ah = g_prev_hi; Al = g_prev_lo; Bw = w_hh;
        bias = b_hh; C = g_gh; K = H_; kstart = 0;
        atomic = false; addBias = true;
    }
    const int KCH = 16;

    float acc[2][8][4];
#pragma unroll
    for (int i = 0; i < 2; i++)
#pragma unroll
        for (int j = 0; j < 8; j++)
#pragma unroll
            for (int r = 0; r < 4; r++) acc[i][j][r] = 0.f;

    const int br = t >> 1, bhf = t & 1;
    const float* Bbase = Bw + (size_t)(n0 + br) * K + kstart + bhf * 16;

    float4 r4[4];
    auto ldgB = [&](int it) {
        const float* p = Bbase + it * 32;
#pragma unroll
        for (int i = 0; i < 4; i++) r4[i] = *reinterpret_cast<const float4*>(p + i * 4);
    };
    auto stsB = [&](int buf) {
        uint32_t h[8];
#pragma unroll
        for (int i = 0; i < 4; i++) {
            h[i * 2]     = f2h2(make_float2(r4[i].x, r4[i].y));
            h[i * 2 + 1] = f2h2(make_float2(r4[i].z, r4[i].w));
        }
        uint32_t d = GT_B + (uint32_t)buf * HTILE + (uint32_t)(br * ROWB + bhf * 32);
        *reinterpret_cast<uint4*>(smem + d)      = make_uint4(h[0], h[1], h[2], h[3]);
        *reinterpret_cast<uint4*>(smem + d + 16) = make_uint4(h[4], h[5], h[6], h[7]);
    };
    auto issueA = [&](int it) {
        uint32_t ring = sb + (uint32_t)(it % 3) * (2 * HTILE);
        int kk = kstart + it * 32;
#pragma unroll
        for (int i = 0; i < 2; i++) {
            int idx = t + i * 256;
            int row = idx >> 2, col = idx & 3;
            uint32_t so = (uint32_t)(row * ROWB + col * 16);
            const size_t ga = (size_t)(m0 + row) * K + kk + col * 8;
            cp_async16(ring + so, Ah + ga);
            cp_async16(ring + HTILE + so, Al + ga);
        }
        cp_commit();
    };

    const int a_row = (lane & 15);
    const int a_kof = ((lane >> 4) & 1) * 16;
    const int b_row = ((lane >> 4) << 3) + (lane & 7);
    const int b_kof = ((lane >> 3) & 1) * 16;
    const int g = lane >> 2, q = lane & 3;

    issueA(0); issueA(1);
    ldgB(0);
    cp_wait<1>();
    stsB(0);
    __syncthreads();

    for (int it = 0; it < KCH; ++it) {
        if (it + 1 < KCH) ldgB(it + 1);
        if (it + 2 < KCH) issueA(it + 2);

        const uint32_t ring = sb + (uint32_t)(it % 3) * (2 * HTILE);
        const uint32_t bT = GT_B + (uint32_t)(it & 1) * HTILE;
#pragma unroll
        for (int ks = 0; ks < 2; ks++) {
            const int kb = ks * 32;
            uint32_t bh[8][2];
#pragma unroll
            for (int njp = 0; njp < 4; njp++) {
                uint32_t addr = sb + bT + (wn * 64 + njp * 16 + b_row) * ROWB + kb + b_kof;
                uint32_t q0, q1, q2, q3;
                ldmx4(q0, q1, q2, q3, addr);
                bh[njp * 2][0] = q0; bh[njp * 2][1] = q1;
                bh[njp * 2 + 1][0] = q2; bh[njp * 2 + 1][1] = q3;
            }
#pragma unroll
            for (int mi = 0; mi < 2; mi++) {
                const uint32_t aro = (wm * 32 + mi * 16 + a_row) * ROWB + kb + a_kof;
                uint32_t ah[4], al[4];
                ldmx4(ah[0], ah[1], ah[2], ah[3], ring + aro);
                ldmx4(al[0], al[1], al[2], al[3], ring + HTILE + aro);
#pragma unroll
                for (int nj = 0; nj < 8; nj++) mma16816(acc[mi][nj], ah, bh[nj]);
#pragma unroll
                for (int nj = 0; nj < 8; nj++) mma16816(acc[mi][nj], al, bh[nj]);
            }
        }
        if (it + 1 < KCH) {
            if (it + 2 < KCH) cp_wait<1>(); else cp_wait<0>();
            stsB((it + 1) & 1);
        }
        __syncthreads();
    }

#pragma unroll
    for (int mi = 0; mi < 2; mi++) {
        int row0 = m0 + wm * 32 + mi * 16 + g;
        int row1 = row0 + 8;
#pragma unroll
        for (int nj = 0; nj < 8; nj++) {
            int col = n0 + wn * 64 + nj * 8 + 2 * q;
            float b0 = addBias ? bias[col] : 0.f;
            float b1 = addBias ? bias[col + 1] : 0.f;
            if (atomic) {
                atomicAdd(&C[(size_t)row0 * G_ + col],     acc[mi][nj][0] + b0);
                atomicAdd(&C[(size_t)row0 * G_ + col + 1], acc[mi][nj][1] + b1);
                atomicAdd(&C[(size_t)row1 * G_ + col],     acc[mi][nj][2] + b0);
                atomicAdd(&C[(size_t)row1 * G_ + col + 1], acc[mi][nj][3] + b1);
            } else {
                float2 o0 = make_float2(acc[mi][nj][0] + b0, acc[mi][nj][1] + b1);
                float2 o1 = make_float2(acc[mi][nj][2] + b0, acc[mi][nj][3] + b1);
                *reinterpret_cast<float2*>(&C[(size_t)row0 * G_ + col]) = o0;
                *reinterpret_cast<float2*>(&C[(size_t)row1 * G_ + col]) = o1;
            }
        }
    }
}

// =====================================================================
// Merged scores kernel (CTA 128x128, warp 32x64, 2 CTA/SM).
// blocks [0, 1024): score_c — A = enc_hi cp.async 3-ring, B = wc_hi 3-ring.
// blocks [1024, 1524): score_g — A = hid_hi cp.async 3-ring, B = Wo LDG->STS.
// =====================================================================
constexpr uint32_t SG_B = 3 * HTILE;
constexpr int SG_SMEM = SG_B + 2 * HTILE;       // 51200
constexpr uint32_t SC_B = 3 * HTILE;
constexpr int SC_SMEM = SC_B + 3 * HTILE;       // 61440
constexpr int SCORES_SMEM = 61440;
constexpr int SC_CTAS = 4 * 256;                // 1024
constexpr int SG_CTAS = NX_ * 2;                // 500

__device__ void sg_body(char* smem, int bx, int by,
                        const __half* __restrict__ Ah,
                        const float* __restrict__ Bf, const float* __restrict__ bias,
                        float* __restrict__ C) {
    const int K = H_, N = V_;
    const int t = threadIdx.x;
    const int lane = t & 31;
    const int wid = t >> 5;
    const int wm = wid & 3, wn = wid >> 2;
    const int m0 = by * 128, n0 = bx * 128;
    const uint32_t sb = smem_u32(smem);

    float acc[2][8][4];
#pragma unroll
    for (int i = 0; i < 2; i++)
#pragma unroll
        for (int j = 0; j < 8; j++)
#pragma unroll
            for (int r = 0; r < 4; r++) acc[i][j][r] = 0.f;

    const int KT = K / 32;   // 16
    const int br = t >> 1, bhf = t & 1;
    const float* Bbase = Bf + (size_t)(n0 + br) * K + bhf * 16;

    float4 r4[4];
    auto ldgB = [&](int it) {
        const float* p = Bbase + it * 32;
#pragma unroll
        for (int i = 0; i < 4; i++) r4[i] = *reinterpret_cast<const float4*>(p + i * 4);
    };
    auto stsB = [&](int buf) {
        uint32_t h[8];
#pragma unroll
        for (int i = 0; i < 4; i++) {
            h[i * 2]     = f2h2(make_float2(r4[i].x, r4[i].y));
            h[i * 2 + 1] = f2h2(make_float2(r4[i].z, r4[i].w));
        }
        uint32_t d = SG_B + (uint32_t)buf * HTILE + (uint32_t)(br * ROWB + bhf * 32);
        *reinterpret_cast<uint4*>(smem + d)      = make_uint4(h[0], h[1], h[2], h[3]);
        *reinterpret_cast<uint4*>(smem + d + 16) = make_uint4(h[4], h[5], h[6], h[7]);
    };
    auto issueA = [&](int it) {
        uint32_t ring = sb + (uint32_t)(it % 3) * HTILE;
        int kk = it * 32;
#pragma unroll
        for (int i = 0; i < 2; i++) {
            int idx = t + i * 256;
            int row = idx >> 2, col = idx & 3;
            uint32_t so = (uint32_t)(row * ROWB + col * 16);
            cp_async16(ring + so, Ah + (size_t)(m0 + row) * K + kk + col * 8);
        }
        cp_commit();
    };

    const int a_row = (lane & 15);
    const int a_kof = ((lane >> 4) & 1) * 16;
    const int b_row = ((lane >> 4) << 3) + (lane & 7);
    const int b_kof = ((lane >> 3) & 1) * 16;
    const int g = lane >> 2, q = lane & 3;

    issueA(0); issueA(1);
    ldgB(0);
    cp_wait<1>();
    stsB(0);
    __syncthreads();

    for (int it = 0; it < KT; ++it) {
        if (it + 1 < KT) ldgB(it + 1);
        if (it + 2 < KT) issueA(it + 2);

        const uint32_t ring = sb + (uint32_t)(it % 3) * HTILE;
        const uint32_t bT = SG_B + (uint32_t)(it & 1) * HTILE;
#pragma unroll
        for (int ks = 0; ks < 2; ks++) {
            const int kb = ks * 32;
            uint32_t bh[8][2];
#pragma unroll
            for (int njp = 0; njp < 4; njp++) {
                uint32_t addr = sb + bT + (wn * 64 + njp * 16 + b_row) * ROWB + kb + b_kof;
                uint32_t q0, q1, q2, q3;
                ldmx4(q0, q1, q2, q3, addr);
                bh[njp * 2][0] = q0; bh[njp * 2][1] = q1;
                bh[njp * 2 + 1][0] = q2; bh[njp * 2 + 1][1] = q3;
            }
#pragma unroll
            for (int mi = 0; mi < 2; mi++) {
                const uint32_t aro = (wm * 32 + mi * 16 + a_row) * ROWB + kb + a_kof;
                uint32_t ah[4];
                ldmx4(ah[0], ah[1], ah[2], ah[3], ring + aro);
#pragma unroll
                for (int nj = 0; nj < 8; nj++) mma16816(acc[mi][nj], ah, bh[nj]);
            }
        }
        if (it + 1 < KT) {
            if (it + 2 < KT) cp_wait<1>(); else cp_wait<0>();
            stsB((it + 1) & 1);
        }
        __syncthreads();
    }

    float pm[4], ps[4];
#pragma unroll
    for (int mi = 0; mi < 2; mi++) {
        float m0v = -1e30f, s0v = 0.f, m1v = -1e30f, s1v = 0.f;
        int row0 = m0 + wm * 32 + mi * 16 + g;
        int row1 = row0 + 8;
#pragma unroll
        for (int nj = 0; nj < 8; nj++) {
            int col = n0 + wn * 64 + nj * 8 + 2 * q;
            float b0 = bias[col], b1 = bias[col + 1];
            float v00 = acc[mi][nj][0] + b0, v01 = acc[mi][nj][1] + b1;
            float v10 = acc[mi][nj][2] + b0, v11 = acc[mi][nj][3] + b1;
            *reinterpret_cast<float2*>(&C[(size_t)row0 * N + col]) = make_float2(v00, v01);
            *reinterpret_cast<float2*>(&C[(size_t)row1 * N + col]) = make_float2(v10, v11);
            msum(m0v, s0v, v00, 1.f); msum(m0v, s0v, v01, 1.f);
            msum(m1v, s1v, v10, 1.f); msum(m1v, s1v, v11, 1.f);
        }
#pragma unroll
        for (int off = 1; off <= 2; off <<= 1) {
            float om = __shfl_xor_sync(0xffffffffu, m0v, off);
            float os = __shfl_xor_sync(0xffffffffu, s0v, off);
            msum(m0v, s0v, om, os);
            om = __shfl_xor_sync(0xffffffffu, m1v, off);
            os = __shfl_xor_sync(0xffffffffu, s1v, off);
            msum(m1v, s1v, om, os);
        }
        pm[mi * 2] = m0v; ps[mi * 2] = s0v;
        pm[mi * 2 + 1] = m1v; ps[mi * 2 + 1] = s1v;
    }
    __syncthreads();
    float* s_pm = reinterpret_cast<float*>(smem);
    float* s_ps = reinterpret_cast<float*>(smem + 512);
    if (wn == 0 && q == 0) {
#pragma unroll
        for (int i = 0; i < 4; i++) {
            int r_in = wm * 32 + (i >> 1) * 16 + g + (i & 1) * 8;
            s_pm[r_in] = pm[i]; s_ps[r_in] = ps[i];
        }
    }
    __syncthreads();
    if (wn == 1 && q == 0) {
#pragma unroll
        for (int i = 0; i < 4; i++) {
            int r_in = wm * 32 + (i >> 1) * 16 + g + (i & 1) * 8;
            float m = pm[i], s = ps[i];
            msum(m, s, s_pm[r_in], s_ps[r_in]);
            g_pmax[(size_t)(m0 + r_in) * NX_ + bx] = m;
            g_psum[(size_t)(m0 + r_in) * NX_ + bx] = s;
        }
    }
}

__device__ void sc_body(char* smem, int bx, int by,
                        const __half* __restrict__ Ah, const __half* __restrict__ Bh16,
                        const float* __restrict__ bias,
                        const float* __restrict__ hidden, float* __restrict__ scOut) {
    const int K = 2 * H_;
    const int t = threadIdx.x;
    const int lane = t & 31;
    const int wid = t >> 5;
    const int wm = wid & 3, wn = wid >> 2;
    const int m0 = by * 128, n0 = bx * 128;
    const uint32_t sb = smem_u32(smem);

    float acc[2][8][4];
#pragma unroll
    for (int i = 0; i < 2; i++)
#pragma unroll
        for (int j = 0; j < 8; j++)
#pragma unroll
            for (int r = 0; r < 4; r++) acc[i][j][r] = 0.f;

    const int KT = K / 32;   // 32

    auto issue = [&](int it) {
        uint32_t ringA = sb + (uint32_t)(it % 3) * HTILE;
        uint32_t ringB = sb + SC_B + (uint32_t)(it % 3) * HTILE;
        int kk = it * 32;
#pragma unroll
        for (int i = 0; i < 2; i++) {
            int idx = t + i * 256;
            int row = idx >> 2, col = idx & 3;
            uint32_t so = (uint32_t)(row * ROWB + col * 16);
            cp_async16(ringA + so, Ah + (size_t)(m0 + row) * K + kk + col * 8);
            cp_async16(ringB + so, Bh16 + (size_t)(n0 + row) * K + kk + col * 8);
        }
        cp_commit();
    };

    const int a_row = (lane & 15);
    const int a_kof = ((lane >> 4) & 1) * 16;
    const int b_row = ((lane >> 4) << 3) + (lane & 7);
    const int b_kof = ((lane >> 3) & 1) * 16;
    const int g = lane >> 2, q = lane & 3;

    issue(0); issue(1);
    for (int it = 0; it < KT; ++it) {
        if (it + 1 < KT) cp_wait<1>(); else cp_wait<0>();
        __syncthreads();
        if (it + 2 < KT) issue(it + 2);

        const uint32_t aT = sb + (uint32_t)(it % 3) * HTILE;
        const uint32_t bT = sb + SC_B + (uint32_t)(it % 3) * HTILE;
#pragma unroll
        for (int ks = 0; ks < 2; ks++) {
            const int kb = ks * 32;
            uint32_t bh[8][2];
#pragma unroll
            for (int njp = 0; njp < 4; njp++) {
                uint32_t addr = bT + (wn * 64 + njp * 16 + b_row) * ROWB + kb + b_kof;
                uint32_t q0, q1, q2, q3;
                ldmx4(q0, q1, q2, q3, addr);
                bh[njp * 2][0] = q0; bh[njp * 2][1] = q1;
                bh[njp * 2 + 1][0] = q2; bh[njp * 2 + 1][1] = q3;
            }
#pragma unroll
            for (int mi = 0; mi < 2; mi++) {
                const uint32_t aro = (wm * 32 + mi * 16 + a_row) * ROWB + kb + a_kof;
                uint32_t ah[4];
                ldmx4(ah[0], ah[1], ah[2], ah[3], aT + aro);
#pragma unroll
                for (int nj = 0; nj < 8; nj++) mma16816(acc[mi][nj], ah, bh[nj]);
            }
        }
        __syncthreads();
    }

    const int b = m0 >> 7;
#pragma unroll
    for (int mi = 0; mi < 2; mi++) {
        float p0 = 0.f, p1 = 0.f;
#pragma unroll
        for (int nj = 0; nj < 8; nj++) {
            int col = n0 + wn * 64 + nj * 8 + 2 * q;
            float bz0 = bias[col], bz1 = bias[col + 1];
            float hv0 = hidden[b * H_ + col], hv1 = hidden[b * H_ + col + 1];
            p0 = fmaf(tanhf(acc[mi][nj][0] + bz0), hv0, p0);
            p0 = fmaf(tanhf(acc[mi][nj][1] + bz1), hv1, p0);
            p1 = fmaf(tanhf(acc[mi][nj][2] + bz0), hv0, p1);
            p1 = fmaf(tanhf(acc[mi][nj][3] + bz1), hv1, p1);
        }
        p0 += __shfl_xor_sync(0xffffffffu, p0, 1);
        p0 += __shfl_xor_sync(0xffffffffu, p0, 2);
        p1 += __shfl_xor_sync(0xffffffffu, p1, 1);
        p1 += __shfl_xor_sync(0xffffffffu, p1, 2);
        if (q == 0) {
            int row = m0 + wm * 32 + mi * 16 + g;
            atomicAdd(&scOut[row], p0);
            atomicAdd(&scOut[row + 8], p1);
        }
    }
}

__global__ void __launch_bounds__(256, 2)
mma_scores(const float* __restrict__ Wc_b,
           const float* __restrict__ Wo_w, const float* __restrict__ Wo_b,
           float* __restrict__ pred) {
    extern __shared__ __align__(16) char smem[];
    const int bid = blockIdx.x;
    if (bid < SC_CTAS) {
        sc_body(smem, bid & 3, bid >> 2, g_enc_hi, g_wc_hi, Wc_b, g_hidden, g_sc);
    } else {
        int id = bid - SC_CTAS;
        sg_body(smem, id % NX_, id / NX_, g_hid_hi, Wo_w, Wo_b, pred);
    }
}

// ---------------- GRU ----------------
__global__ void gru_kernel(const float* __restrict__ prev,
                           float* __restrict__ outHidden) {
    int idx = blockIdx.x * blockDim.x + threadIdx.x;
    int b = idx >> 9, h = idx & (H_ - 1);
    const float* gi = g_gi + (size_t)b * G_;
    const float* gh = g_gh + (size_t)b * G_;
    float ir = gi[h], iz = gi[h + H_], inn = gi[h + 2 * H_];
    float hr = gh[h], hz = gh[h + H_], hn = gh[h + 2 * H_];
    float r = 1.f / (1.f + expf(-(ir + hr)));
    float z = 1.f / (1.f + expf(-(iz + hz)));
    float n = tanhf(inn + r * hn);
    float hv = (1.f - z) * n + z * prev[idx];
    g_hidden[idx] = hv;
    outHidden[idx] = hv;
    g_hid_hi[idx] = __float2half_rn(hv);
}

// ---------------- softmax ----------------
__global__ void __launch_bounds__(512)
softmax_kernel(float* __restrict__ pred, const int* __restrict__ src,
               const int* __restrict__ ids) {
    __shared__ float s_lc[S_];
    __shared__ float s_m[512];
    __shared__ float s_s[512];
    __shared__ int s_cnt;
    const int b = blockIdx.x, t = threadIdx.x;
    float* row = pred + (size_t)b * V_;

    if (t == 0) s_cnt = 0;
    if (t < S_) {
        float mask = (src[b * S_ + t] == 0) ? -1000.f : 0.f;
        s_lc[t] = tanhf(g_sc[b * S_ + t] + mask);
    }
    __syncthreads();

    float m = -1e30f, s = 0.f;
    for (int x = t; x < NX_; x += 512)
        msum(m, s, g_pmax[(size_t)b * NX_ + x], g_psum[(size_t)b * NX_ + x]);
    if (t < S_) msum(m, s, s_lc[t], 1.f);
    s_m[t] = m; s_s[t] = s;
    __syncthreads();
    for (int o = 256; o; o >>= 1) {
        if (t < o) {
            float mm = s_m[t], ss = s_s[t];
            msum(mm, ss, s_m[t + o], s_s[t + o]);
            s_m[t] = mm; s_s[t] = ss;
        }
        __syncthreads();
    }
    float gmax = s_m[0];
    float inv = 1.f / s_s[0];

    for (int v = t; v < V_; v += 512) row[v] = __expf(row[v] - gmax) * inv;

    int id = ids[b];
    if (t < S_ && src[b * S_ + t] == id) atomicAdd(&s_cnt, 1);
    __syncthreads();

    if (t < S_) {
        float pc = __expf(s_lc[t] - gmax) * inv;
        atomicAdd(&row[src[b * S_ + t]], pc);
        float eq = (src[b * S_ + t] == id) ? 1.f : 0.f;
        g_attn[b * S_ + t] = pc * eq / fmaxf((float)s_cnt, 1.f);
    }
}

__global__ void __launch_bounds__(256)
weighted_kernel(const float* __restrict__ enc, float* __restrict__ outW) {
    __shared__ float s_a[S_];
    const int b = blockIdx.x, t = threadIdx.x;
    if (t < S_) s_a[t] = g_attn[b * S_ + t];
    __syncthreads();
    float4 acc = make_float4(0.f, 0.f, 0.f, 0.f);
    const float4* e4 = reinterpret_cast<const float4*>(enc + (size_t)b * S_ * (2 * H_));
    for (int s = 0; s < S_; s++) {
        float w = s_a[s];
        if (w != 0.f) {
            float4 e = e4[s * 256 + t];
            acc.x = fmaf(w, e.x, acc.x); acc.y = fmaf(w, e.y, acc.y);
            acc.z = fmaf(w, e.z, acc.z); acc.w = fmaf(w, e.w, acc.w);
        }
    }
    reinterpret_cast<float4*>(outW)[b * 256 + t] = acc;
}

// ---------------- launch ----------------
extern "C" void kernel_launch(void* const* d_in, const int* in_sizes, int n_in,
                              void* d_out, int out_size) {
    const int*   input_ids = (const int*)d_in[0];
    const float* encoded   = (const float*)d_in[1];
    const int*   src       = (const int*)d_in[2];
    const float* prev      = (const float*)d_in[3];
    const float* weighted  = (const float*)d_in[4];
    const float* embed_w   = (const float*)d_in[6];
    const float* w_ih      = (const float*)d_in[7];
    const float* w_hh      = (const float*)d_in[8];
    const float* b_ih      = (const float*)d_in[9];
    const float* b_hh      = (const float*)d_in[10];
    const float* Wo_w      = (const float*)d_in[13];
    const float* Wo_b      = (const float*)d_in[14];
    const float* Wc_w      = (const float*)d_in[15];
    const float* Wc_b      = (const float*)d_in[16];

    float* pred        = (float*)d_out;
    float* outHidden   = pred + (size_t)B_ * V_;
    float* outWeighted = outHidden + (size_t)B_ * H_;

    cudaFuncSetAttribute(mma_gates, cudaFuncAttributeMaxDynamicSharedMemorySize, GATES_SMEM);
    cudaFuncSetAttribute(mma_scores, cudaFuncAttributeMaxDynamicSharedMemorySize, SCORES_SMEM);

    prep_kernel<<<PREP_CTAS, 256>>>(input_ids, embed_w, weighted, prev, Wc_w);

    // gates GEMM (96 CTAs) + enc fp16 split (512 CTAs), one launch
    mma_gates<<<GATES_CTAS, 256, GATES_SMEM>>>(b_ih, b_hh, w_ih, w_hh, encoded);

    gru_kernel<<<(B_ * H_) / 256, 256>>>(prev, outHidden);

    mma_scores<<<SC_CTAS + SG_CTAS, 256, SCORES_SMEM>>>(Wc_b, Wo_w, Wo_b, pred);

    softmax_kernel<<<B_, 512>>>(pred, src, input_ids);

    weighted_kernel<<<B_, 256>>>(encoded, outWeighted);

    (void)in_sizes; (void)n_in; (void)out_size;
}

// round 16
// speedup vs baseline: 1.5834x; 1.0082x over previous
#include <cuda_runtime.h>
#include <cuda_fp16.h>
#include <math.h>
#include <stdint.h>

namespace {
constexpr int B_ = 256;
constexpr int S_ = 128;
constexpr int H_ = 512;
constexpr int E_ = 512;
constexpr int V_ = 32000;
constexpr int IN_ = E_ + 2 * H_;   // 1536
constexpr int G_ = 3 * H_;         // 1536
constexpr int NX_ = V_ / 128;      // 250
}

// ---------------- static scratch ----------------
__device__ float g_gi[B_ * G_];
__device__ float g_gh[B_ * G_];
__device__ float g_hidden[B_ * H_];
__device__ float g_sc[B_ * S_];
__device__ float g_pmax[B_ * NX_];
__device__ float g_psum[B_ * NX_];
__device__ __half g_x_hi[B_ * IN_];
__device__ __half g_x_lo[B_ * IN_];
__device__ __half g_prev_hi[B_ * H_];
__device__ __half g_prev_lo[B_ * H_];
__device__ __half g_wc_hi[H_ * 2 * H_];
__device__ __half g_enc_hi[B_ * S_ * 2 * H_];
__device__ __half g_hid_hi[B_ * H_];

// ---------------- helpers ----------------
__device__ __forceinline__ void cp_async16(uint32_t s, const void* g) {
    asm volatile("cp.async.cg.shared.global [%0], [%1], 16;\n"
                 :: "r"(s), "l"(g) : "memory");
}
__device__ __forceinline__ void cp_commit() {
    asm volatile("cp.async.commit_group;\n" ::: "memory");
}
template <int N>
__device__ __forceinline__ void cp_wait() {
    asm volatile("cp.async.wait_group %0;\n" :: "n"(N) : "memory");
}
__device__ __forceinline__ uint32_t smem_u32(const void* p) {
    uint32_t a;
    asm("{ .reg .u64 t; cvta.to.shared.u64 t, %1; cvt.u32.u64 %0, t; }"
        : "=r"(a) : "l"(p));
    return a;
}
__device__ __forceinline__ void ldmx4(uint32_t& r0, uint32_t& r1, uint32_t& r2,
                                      uint32_t& r3, uint32_t addr) {
    asm volatile("ldmatrix.sync.aligned.m8n8.x4.shared.b16 {%0,%1,%2,%3}, [%4];\n"
                 : "=r"(r0), "=r"(r1), "=r"(r2), "=r"(r3) : "r"(addr));
}
__device__ __forceinline__ void mma16816(float* d, const uint32_t* a,
                                         const uint32_t* b) {
    asm volatile(
        "mma.sync.aligned.m16n8k16.row.col.f32.f16.f16.f32 "
        "{%0,%1,%2,%3}, {%4,%5,%6,%7}, {%8,%9}, {%0,%1,%2,%3};\n"
        : "+f"(d[0]), "+f"(d[1]), "+f"(d[2]), "+f"(d[3])
        : "r"(a[0]), "r"(a[1]), "r"(a[2]), "r"(a[3]), "r"(b[0]), "r"(b[1]));
}
__device__ __forceinline__ uint32_t f2h2(float2 f) {
    __half2 h = __float22half2_rn(f);
    return *reinterpret_cast<uint32_t*>(&h);
}
__device__ __forceinline__ void split2h(float2 f, uint32_t& hi, uint32_t& lo) {
    hi = f2h2(f);
    __half2 hh = *reinterpret_cast<__half2*>(&hi);
    float2 fh = __half22float2(hh);
    lo = f2h2(make_float2(f.x - fh.x, f.y - fh.y));
}
__device__ __forceinline__ uint2 h4_of(float4 v) {
    return make_uint2(f2h2(make_float2(v.x, v.y)), f2h2(make_float2(v.z, v.w)));
}
__device__ __forceinline__ void hl4_of(float4 v, uint2& h, uint2& l) {
    uint32_t h0, h1, l0, l1;
    split2h(make_float2(v.x, v.y), h0, l0);
    split2h(make_float2(v.z, v.w), h1, l1);
    h = make_uint2(h0, h1); l = make_uint2(l0, l1);
}
__device__ __forceinline__ void msum(float& m, float& s, float om, float os) {
    float nm = fmaxf(m, om);
    s = s * __expf(m - nm) + os * __expf(om - nm);
    m = nm;
}

// =====================================================================
// Fused prep: x split, prev split, Wc hi, zero gi, zero sc
// =====================================================================
constexpr int PC0 = 96, PC1 = 32, PC4 = 512, PC5 = 96, PC6 = 8;
constexpr int PREP_CTAS = PC0 + PC1 + PC4 + PC5 + PC6;   // 744

__global__ void __launch_bounds__(256)
prep_kernel(const int* __restrict__ ids, const float* __restrict__ emb,
            const float* __restrict__ weighted, const float* __restrict__ prev,
            const float* __restrict__ Wc_w) {
    int bid = blockIdx.x;
    const int tid = threadIdx.x;
    if (bid < PC0) {
        const int n4 = B_ * IN_ / 4, T = PC0 * 256, J4 = IN_ / 4;
        for (int i = bid * 256 + tid; i < n4; i += T) {
            int b = i / J4, j = (i - b * J4) * 4;
            float4 v = (j < E_)
                ? *reinterpret_cast<const float4*>(emb + (size_t)ids[b] * E_ + j)
                : *reinterpret_cast<const float4*>(weighted + (size_t)b * 2 * H_ + (j - E_));
            uint2 h, l; hl4_of(v, h, l);
            *reinterpret_cast<uint2*>(g_x_hi + (size_t)i * 4) = h;
            *reinterpret_cast<uint2*>(g_x_lo + (size_t)i * 4) = l;
        }
        return;
    }
    bid -= PC0;
    if (bid < PC1) {
        const int n4 = B_ * H_ / 4, T = PC1 * 256;
        const float4* s4 = reinterpret_cast<const float4*>(prev);
        for (int i = bid * 256 + tid; i < n4; i += T) {
            uint2 h, l; hl4_of(s4[i], h, l);
            *reinterpret_cast<uint2*>(g_prev_hi + (size_t)i * 4) = h;
            *reinterpret_cast<uint2*>(g_prev_lo + (size_t)i * 4) = l;
        }
        return;
    }
    bid -= PC1;
    if (bid < PC4) {
        const int n4 = H_ * 2 * H_ / 4, T = PC4 * 256;
        const float4* s4 = reinterpret_cast<const float4*>(Wc_w);
        for (int i = bid * 256 + tid; i < n4; i += T)
            *reinterpret_cast<uint2*>(g_wc_hi + (size_t)i * 4) = h4_of(s4[i]);
        return;
    }
    bid -= PC4;
    if (bid < PC5) {
        const int n4 = B_ * G_ / 4, T = PC5 * 256;
        float4* p = reinterpret_cast<float4*>(g_gi);
        for (int i = bid * 256 + tid; i < n4; i += T)
            p[i] = make_float4(0.f, 0.f, 0.f, 0.f);
        return;
    }
    bid -= PC5;
    {
        const int n4 = B_ * S_ / 4, T = PC6 * 256;
        float4* p = reinterpret_cast<float4*>(g_sc);
        for (int i = bid * 256 + tid; i < n4; i += T)
            p[i] = make_float4(0.f, 0.f, 0.f, 0.f);
    }
}

// ---------------- common GEMM constants ----------------
constexpr int ROWB = 80;
constexpr int HTILE = 128 * ROWB;          // 10240 B

// =====================================================================
// Gates + enc split in ONE launch (unchanged from R15).
// =====================================================================
constexpr int GATES_GEMM = 96;
constexpr int GATES_SPLIT = 512;
constexpr int GATES_CTAS = GATES_GEMM + GATES_SPLIT;
constexpr uint32_t GT_B = 3 * 2 * HTILE;        // 61440
constexpr int GATES_SMEM = GT_B + 2 * HTILE;    // 81920

__global__ void __launch_bounds__(256, 2)
mma_gates(const float* __restrict__ b_ih, const float* __restrict__ b_hh,
          const float* __restrict__ w_ih, const float* __restrict__ w_hh,
          const float* __restrict__ enc) {
    extern __shared__ __align__(16) char smem[];
    const int t = threadIdx.x;

    if (blockIdx.x >= GATES_GEMM) {
        const int sbid = blockIdx.x - GATES_GEMM;
        const int n4 = B_ * S_ * 2 * H_ / 4;
        const int T = GATES_SPLIT * 256;
        const float4* s4 = reinterpret_cast<const float4*>(enc);
        uint2* h4 = reinterpret_cast<uint2*>(g_enc_hi);
        int i = sbid * 256 + t;
        for (; i + 3 * T < n4; i += 4 * T) {
            float4 v0 = s4[i], v1 = s4[i + T], v2 = s4[i + 2 * T], v3 = s4[i + 3 * T];
            h4[i] = h4_of(v0); h4[i + T] = h4_of(v1);
            h4[i + 2 * T] = h4_of(v2); h4[i + 3 * T] = h4_of(v3);
        }
        for (; i < n4; i += T) h4[i] = h4_of(s4[i]);
        return;
    }

    const int z = blockIdx.x / 24;
    const int rem = blockIdx.x % 24;
    const int by = rem / 12, bx = rem % 12;
    const int lane = t & 31;
    const int wid = t >> 5;
    const int wm = wid & 3, wn = wid >> 2;
    const int m0 = by * 128, n0 = bx * 128;
    const uint32_t sb = smem_u32(smem);

    const __half *Ah, *Al;
    const float *Bw, *bias;
    float* C;
    int K, kstart;
    bool atomic, addBias;
    if (z < 3) {
        Ah = g_x_hi; Al = g_x_lo; Bw = w_ih;
        bias = b_ih; C = g_gi; K = IN_; kstart = z * 512;
        atomic = true; addBias = (z == 0);
    } else {
        Ah = g_prev_hi; Al = g_prev_lo; Bw = w_hh;
        bias = b_hh; C = g_gh; K = H_; kstart = 0;
        atomic = false; addBias = true;
    }
    const int KCH = 16;

    float acc[2][8][4];
#pragma unroll
    for (int i = 0; i < 2; i++)
#pragma unroll
        for (int j = 0; j < 8; j++)
#pragma unroll
            for (int r = 0; r < 4; r++) acc[i][j][r] = 0.f;

    const int br = t >> 1, bhf = t & 1;
    const float* Bbase = Bw + (size_t)(n0 + br) * K + kstart + bhf * 16;

    float4 r4[4];
    auto ldgB = [&](int it) {
        const float* p = Bbase + it * 32;
#pragma unroll
        for (int i = 0; i < 4; i++) r4[i] = *reinterpret_cast<const float4*>(p + i * 4);
    };
    auto stsB = [&](int buf) {
        uint32_t h[8];
#pragma unroll
        for (int i = 0; i < 4; i++) {
            h[i * 2]     = f2h2(make_float2(r4[i].x, r4[i].y));
            h[i * 2 + 1] = f2h2(make_float2(r4[i].z, r4[i].w));
        }
        uint32_t d = GT_B + (uint32_t)buf * HTILE + (uint32_t)(br * ROWB + bhf * 32);
        *reinterpret_cast<uint4*>(smem + d)      = make_uint4(h[0], h[1], h[2], h[3]);
        *reinterpret_cast<uint4*>(smem + d + 16) = make_uint4(h[4], h[5], h[6], h[7]);
    };
    auto issueA = [&](int it) {
        uint32_t ring = sb + (uint32_t)(it % 3) * (2 * HTILE);
        int kk = kstart + it * 32;
#pragma unroll
        for (int i = 0; i < 2; i++) {
            int idx = t + i * 256;
            int row = idx >> 2, col = idx & 3;
            uint32_t so = (uint32_t)(row * ROWB + col * 16);
            const size_t ga = (size_t)(m0 + row) * K + kk + col * 8;
            cp_async16(ring + so, Ah + ga);
            cp_async16(ring + HTILE + so, Al + ga);
        }
        cp_commit();
    };

    const int a_row = (lane & 15);
    const int a_kof = ((lane >> 4) & 1) * 16;
    const int b_row = ((lane >> 4) << 3) + (lane & 7);
    const int b_kof = ((lane >> 3) & 1) * 16;
    const int g = lane >> 2, q = lane & 3;

    issueA(0); issueA(1);
    ldgB(0);
    cp_wait<1>();
    stsB(0);
    __syncthreads();

    for (int it = 0; it < KCH; ++it) {
        if (it + 1 < KCH) ldgB(it + 1);
        if (it + 2 < KCH) issueA(it + 2);

        const uint32_t ring = sb + (uint32_t)(it % 3) * (2 * HTILE);
        const uint32_t bT = GT_B + (uint32_t)(it & 1) * HTILE;
#pragma unroll
        for (int ks = 0; ks < 2; ks++) {
            const int kb = ks * 32;
            uint32_t bh[8][2];
#pragma unroll
            for (int njp = 0; njp < 4; njp++) {
                uint32_t addr = sb + bT + (wn * 64 + njp * 16 + b_row) * ROWB + kb + b_kof;
                uint32_t q0, q1, q2, q3;
                ldmx4(q0, q1, q2, q3, addr);
                bh[njp * 2][0] = q0; bh[njp * 2][1] = q1;
                bh[njp * 2 + 1][0] = q2; bh[njp * 2 + 1][1] = q3;
            }
#pragma unroll
            for (int mi = 0; mi < 2; mi++) {
                const uint32_t aro = (wm * 32 + mi * 16 + a_row) * ROWB + kb + a_kof;
                uint32_t ah[4], al[4];
                ldmx4(ah[0], ah[1], ah[2], ah[3], ring + aro);
                ldmx4(al[0], al[1], al[2], al[3], ring + HTILE + aro);
#pragma unroll
                for (int nj = 0; nj < 8; nj++) mma16816(acc[mi][nj], ah, bh[nj]);
#pragma unroll
                for (int nj = 0; nj < 8; nj++) mma16816(acc[mi][nj], al, bh[nj]);
            }
        }
        if (it + 1 < KCH) {
            if (it + 2 < KCH) cp_wait<1>(); else cp_wait<0>();
            stsB((it + 1) & 1);
        }
        __syncthreads();
    }

#pragma unroll
    for (int mi = 0; mi < 2; mi++) {
        int row0 = m0 + wm * 32 + mi * 16 + g;
        int row1 = row0 + 8;
#pragma unroll
        for (int nj = 0; nj < 8; nj++) {
            int col = n0 + wn * 64 + nj * 8 + 2 * q;
            float b0 = addBias ? bias[col] : 0.f;
            float b1 = addBias ? bias[col + 1] : 0.f;
            if (atomic) {
                atomicAdd(&C[(size_t)row0 * G_ + col],     acc[mi][nj][0] + b0);
                atomicAdd(&C[(size_t)row0 * G_ + col + 1], acc[mi][nj][1] + b1);
                atomicAdd(&C[(size_t)row1 * G_ + col],     acc[mi][nj][2] + b0);
                atomicAdd(&C[(size_t)row1 * G_ + col + 1], acc[mi][nj][3] + b1);
            } else {
                float2 o0 = make_float2(acc[mi][nj][0] + b0, acc[mi][nj][1] + b1);
                float2 o1 = make_float2(acc[mi][nj][2] + b0, acc[mi][nj][3] + b1);
                *reinterpret_cast<float2*>(&C[(size_t)row0 * G_ + col]) = o0;
                *reinterpret_cast<float2*>(&C[(size_t)row1 * G_ + col]) = o1;
            }
        }
    }
}

// =====================================================================
// Merged scores kernel (CTA 128x128, warp 32x64, 2 CTA/SM).
// =====================================================================
constexpr uint32_t SG_B = 3 * HTILE;
constexpr int SG_SMEM = SG_B + 2 * HTILE;       // 51200
constexpr uint32_t SC_B = 3 * HTILE;
constexpr int SC_SMEM = SC_B + 3 * HTILE;       // 61440
constexpr int SCORES_SMEM = 61440;
constexpr int SC_CTAS = 4 * 256;                // 1024
constexpr int SG_CTAS = NX_ * 2;                // 500

__device__ void sg_body(char* smem, int bx, int by,
                        const __half* __restrict__ Ah,
                        const float* __restrict__ Bf, const float* __restrict__ bias,
                        float* __restrict__ C) {
    const int K = H_, N = V_;
    const int t = threadIdx.x;
    const int lane = t & 31;
    const int wid = t >> 5;
    const int wm = wid & 3, wn = wid >> 2;
    const int m0 = by * 128, n0 = bx * 128;
    const uint32_t sb = smem_u32(smem);

    float acc[2][8][4];
#pragma unroll
    for (int i = 0; i < 2; i++)
#pragma unroll
        for (int j = 0; j < 8; j++)
#pragma unroll
            for (int r = 0; r < 4; r++) acc[i][j][r] = 0.f;

    const int KT = K / 32;   // 16
    const int br = t >> 1, bhf = t & 1;
    const float* Bbase = Bf + (size_t)(n0 + br) * K + bhf * 16;

    float4 r4[4];
    auto ldgB = [&](int it) {
        const float* p = Bbase + it * 32;
#pragma unroll
        for (int i = 0; i < 4; i++) r4[i] = *reinterpret_cast<const float4*>(p + i * 4);
    };
    auto stsB = [&](int buf) {
        uint32_t h[8];
#pragma unroll
        for (int i = 0; i < 4; i++) {
            h[i * 2]     = f2h2(make_float2(r4[i].x, r4[i].y));
            h[i * 2 + 1] = f2h2(make_float2(r4[i].z, r4[i].w));
        }
        uint32_t d = SG_B + (uint32_t)buf * HTILE + (uint32_t)(br * ROWB + bhf * 32);
        *reinterpret_cast<uint4*>(smem + d)      = make_uint4(h[0], h[1], h[2], h[3]);
        *reinterpret_cast<uint4*>(smem + d + 16) = make_uint4(h[4], h[5], h[6], h[7]);
    };
    auto issueA = [&](int it) {
        uint32_t ring = sb + (uint32_t)(it % 3) * HTILE;
        int kk = it * 32;
#pragma unroll
        for (int i = 0; i < 2; i++) {
            int idx = t + i * 256;
            int row = idx >> 2, col = idx & 3;
            uint32_t so = (uint32_t)(row * ROWB + col * 16);
            cp_async16(ring + so, Ah + (size_t)(m0 + row) * K + kk + col * 8);
        }
        cp_commit();
    };

    const int a_row = (lane & 15);
    const int a_kof = ((lane >> 4) & 1) * 16;
    const int b_row = ((lane >> 4) << 3) + (lane & 7);
    const int b_kof = ((lane >> 3) & 1) * 16;
    const int g = lane >> 2, q = lane & 3;

    issueA(0); issueA(1);
    ldgB(0);
    cp_wait<1>();
    stsB(0);
    __syncthreads();

    for (int it = 0; it < KT; ++it) {
        if (it + 1 < KT) ldgB(it + 1);
        if (it + 2 < KT) issueA(it + 2);

        const uint32_t ring = sb + (uint32_t)(it % 3) * HTILE;
        const uint32_t bT = SG_B + (uint32_t)(it & 1) * HTILE;
#pragma unroll
        for (int ks = 0; ks < 2; ks++) {
            const int kb = ks * 32;
            uint32_t bh[8][2];
#pragma unroll
            for (int njp = 0; njp < 4; njp++) {
                uint32_t addr = sb + bT + (wn * 64 + njp * 16 + b_row) * ROWB + kb + b_kof;
                uint32_t q0, q1, q2, q3;
                ldmx4(q0, q1, q2, q3, addr);
                bh[njp * 2][0] = q0; bh[njp * 2][1] = q1;
                bh[njp * 2 + 1][0] = q2; bh[njp * 2 + 1][1] = q3;
            }
#pragma unroll
            for (int mi = 0; mi < 2; mi++) {
                const uint32_t aro = (wm * 32 + mi * 16 + a_row) * ROWB + kb + a_kof;
                uint32_t ah[4];
                ldmx4(ah[0], ah[1], ah[2], ah[3], ring + aro);
#pragma unroll
                for (int nj = 0; nj < 8; nj++) mma16816(acc[mi][nj], ah, bh[nj]);
            }
        }
        if (it + 1 < KT) {
            if (it + 2 < KT) cp_wait<1>(); else cp_wait<0>();
            stsB((it + 1) & 1);
        }
        __syncthreads();
    }

    float pm[4], ps[4];
#pragma unroll
    for (int mi = 0; mi < 2; mi++) {
        float m0v = -1e30f, s0v = 0.f, m1v = -1e30f, s1v = 0.f;
        int row0 = m0 + wm * 32 + mi * 16 + g;
        int row1 = row0 + 8;
#pragma unroll
        for (int nj = 0; nj < 8; nj++) {
            int col = n0 + wn * 64 + nj * 8 + 2 * q;
            float b0 = bias[col], b1 = bias[col + 1];
            float v00 = acc[mi][nj][0] + b0, v01 = acc[mi][nj][1] + b1;
            float v10 = acc[mi][nj][2] + b0, v11 = acc[mi][nj][3] + b1;
            *reinterpret_cast<float2*>(&C[(size_t)row0 * N + col]) = make_float2(v00, v01);
            *reinterpret_cast<float2*>(&C[(size_t)row1 * N + col]) = make_float2(v10, v11);
            msum(m0v, s0v, v00, 1.f); msum(m0v, s0v, v01, 1.f);
            msum(m1v, s1v, v10, 1.f); msum(m1v, s1v, v11, 1.f);
        }
#pragma unroll
        for (int off = 1; off <= 2; off <<= 1) {
            float om = __shfl_xor_sync(0xffffffffu, m0v, off);
            float os = __shfl_xor_sync(0xffffffffu, s0v, off);
            msum(m0v, s0v, om, os);
            om = __shfl_xor_sync(0xffffffffu, m1v, off);
            os = __shfl_xor_sync(0xffffffffu, s1v, off);
            msum(m1v, s1v, om, os);
        }
        pm[mi * 2] = m0v; ps[mi * 2] = s0v;
        pm[mi * 2 + 1] = m1v; ps[mi * 2 + 1] = s1v;
    }
    __syncthreads();
    float* s_pm = reinterpret_cast<float*>(smem);
    float* s_ps = reinterpret_cast<float*>(smem + 512);
    if (wn == 0 && q == 0) {
#pragma unroll
        for (int i = 0; i < 4; i++) {
            int r_in = wm * 32 + (i >> 1) * 16 + g + (i & 1) * 8;
            s_pm[r_in] = pm[i]; s_ps[r_in] = ps[i];
        }
    }
    __syncthreads();
    if (wn == 1 && q == 0) {
#pragma unroll
        for (int i = 0; i < 4; i++) {
            int r_in = wm * 32 + (i >> 1) * 16 + g + (i & 1) * 8;
            float m = pm[i], s = ps[i];
            msum(m, s, s_pm[r_in], s_ps[r_in]);
            g_pmax[(size_t)(m0 + r_in) * NX_ + bx] = m;
            g_psum[(size_t)(m0 + r_in) * NX_ + bx] = s;
        }
    }
}

__device__ void sc_body(char* smem, int bx, int by,
                        const __half* __restrict__ Ah, const __half* __restrict__ Bh16,
                        const float* __restrict__ bias,
                        const float* __restrict__ hidden, float* __restrict__ scOut) {
    const int K = 2 * H_;
    const int t = threadIdx.x;
    const int lane = t & 31;
    const int wid = t >> 5;
    const int wm = wid & 3, wn = wid >> 2;
    const int m0 = by * 128, n0 = bx * 128;
    const uint32_t sb = smem_u32(smem);

    float acc[2][8][4];
#pragma unroll
    for (int i = 0; i < 2; i++)
#pragma unroll
        for (int j = 0; j < 8; j++)
#pragma unroll
            for (int r = 0; r < 4; r++) acc[i][j][r] = 0.f;

    const int KT = K / 32;   // 32

    auto issue = [&](int it) {
        uint32_t ringA = sb + (uint32_t)(it % 3) * HTILE;
        uint32_t ringB = sb + SC_B + (uint32_t)(it % 3) * HTILE;
        int kk = it * 32;
#pragma unroll
        for (int i = 0; i < 2; i++) {
            int idx = t + i * 256;
            int row = idx >> 2, col = idx & 3;
            uint32_t so = (uint32_t)(row * ROWB + col * 16);
            cp_async16(ringA + so, Ah + (size_t)(m0 + row) * K + kk + col * 8);
            cp_async16(ringB + so, Bh16 + (size_t)(n0 + row) * K + kk + col * 8);
        }
        cp_commit();
    };

    const int a_row = (lane & 15);
    const int a_kof = ((lane >> 4) & 1) * 16;
    const int b_row = ((lane >> 4) << 3) + (lane & 7);
    const int b_kof = ((lane >> 3) & 1) * 16;
    const int g = lane >> 2, q = lane & 3;

    issue(0); issue(1);
    for (int it = 0; it < KT; ++it) {
        if (it + 1 < KT) cp_wait<1>(); else cp_wait<0>();
        __syncthreads();   // single barrier per iter (3-deep ring gives slack)
        if (it + 2 < KT) issue(it + 2);

        const uint32_t aT = sb + (uint32_t)(it % 3) * HTILE;
        const uint32_t bT = sb + SC_B + (uint32_t)(it % 3) * HTILE;
#pragma unroll
        for (int ks = 0; ks < 2; ks++) {
            const int kb = ks * 32;
            uint32_t bh[8][2];
#pragma unroll
            for (int njp = 0; njp < 4; njp++) {
                uint32_t addr = bT + (wn * 64 + njp * 16 + b_row) * ROWB + kb + b_kof;
                uint32_t q0, q1, q2, q3;
                ldmx4(q0, q1, q2, q3, addr);
                bh[njp * 2][0] = q0; bh[njp * 2][1] = q1;
                bh[njp * 2 + 1][0] = q2; bh[njp * 2 + 1][1] = q3;
            }
#pragma unroll
            for (int mi = 0; mi < 2; mi++) {
                const uint32_t aro = (wm * 32 + mi * 16 + a_row) * ROWB + kb + a_kof;
                uint32_t ah[4];
                ldmx4(ah[0], ah[1], ah[2], ah[3], aT + aro);
#pragma unroll
                for (int nj = 0; nj < 8; nj++) mma16816(acc[mi][nj], ah, bh[nj]);
            }
        }
    }

    const int b = m0 >> 7;
#pragma unroll
    for (int mi = 0; mi < 2; mi++) {
        float p0 = 0.f, p1 = 0.f;
#pragma unroll
        for (int nj = 0; nj < 8; nj++) {
            int col = n0 + wn * 64 + nj * 8 + 2 * q;
            float bz0 = bias[col], bz1 = bias[col + 1];
            float hv0 = hidden[b * H_ + col], hv1 = hidden[b * H_ + col + 1];
            p0 = fmaf(tanhf(acc[mi][nj][0] + bz0), hv0, p0);
            p0 = fmaf(tanhf(acc[mi][nj][1] + bz1), hv1, p0);
            p1 = fmaf(tanhf(acc[mi][nj][2] + bz0), hv0, p1);
            p1 = fmaf(tanhf(acc[mi][nj][3] + bz1), hv1, p1);
        }
        p0 += __shfl_xor_sync(0xffffffffu, p0, 1);
        p0 += __shfl_xor_sync(0xffffffffu, p0, 2);
        p1 += __shfl_xor_sync(0xffffffffu, p1, 1);
        p1 += __shfl_xor_sync(0xffffffffu, p1, 2);
        if (q == 0) {
            int row = m0 + wm * 32 + mi * 16 + g;
            atomicAdd(&scOut[row], p0);
            atomicAdd(&scOut[row + 8], p1);
        }
    }
}

__global__ void __launch_bounds__(256, 2)
mma_scores(const float* __restrict__ Wc_b,
           const float* __restrict__ Wo_w, const float* __restrict__ Wo_b,
           float* __restrict__ pred) {
    extern __shared__ __align__(16) char smem[];
    const int bid = blockIdx.x;
    if (bid < SC_CTAS) {
        sc_body(smem, bid & 3, bid >> 2, g_enc_hi, g_wc_hi, Wc_b, g_hidden, g_sc);
    } else {
        int id = bid - SC_CTAS;
        sg_body(smem, id % NX_, id / NX_, g_hid_hi, Wo_w, Wo_b, pred);
    }
}

// ---------------- GRU ----------------
__global__ void gru_kernel(const float* __restrict__ prev,
                           float* __restrict__ outHidden) {
    int idx = blockIdx.x * blockDim.x + threadIdx.x;
    int b = idx >> 9, h = idx & (H_ - 1);
    const float* gi = g_gi + (size_t)b * G_;
    const float* gh = g_gh + (size_t)b * G_;
    float ir = gi[h], iz = gi[h + H_], inn = gi[h + 2 * H_];
    float hr = gh[h], hz = gh[h + H_], hn = gh[h + 2 * H_];
    float r = 1.f / (1.f + expf(-(ir + hr)));
    float z = 1.f / (1.f + expf(-(iz + hz)));
    float n = tanhf(inn + r * hn);
    float hv = (1.f - z) * n + z * prev[idx];
    g_hidden[idx] = hv;
    outHidden[idx] = hv;
    g_hid_hi[idx] = __float2half_rn(hv);
}

// ---------------- softmax + weighted_out (merged) ----------------
__global__ void __launch_bounds__(512)
softmax_weighted_kernel(float* __restrict__ pred, const int* __restrict__ src,
                        const int* __restrict__ ids,
                        const float* __restrict__ enc,
                        float* __restrict__ outW) {
    __shared__ float s_lc[S_];
    __shared__ float s_att[S_];
    __shared__ float s_m[512];
    __shared__ float s_s[512];
    __shared__ int s_cnt;
    const int b = blockIdx.x, t = threadIdx.x;
    float* row = pred + (size_t)b * V_;

    if (t == 0) s_cnt = 0;
    if (t < S_) {
        float mask = (src[b * S_ + t] == 0) ? -1000.f : 0.f;
        s_lc[t] = tanhf(g_sc[b * S_ + t] + mask);
    }
    __syncthreads();

    float m = -1e30f, s = 0.f;
    for (int x = t; x < NX_; x += 512)
        msum(m, s, g_pmax[(size_t)b * NX_ + x], g_psum[(size_t)b * NX_ + x]);
    if (t < S_) msum(m, s, s_lc[t], 1.f);
    s_m[t] = m; s_s[t] = s;
    __syncthreads();
    for (int o = 256; o; o >>= 1) {
        if (t < o) {
            float mm = s_m[t], ss = s_s[t];
            msum(mm, ss, s_m[t + o], s_s[t + o]);
            s_m[t] = mm; s_s[t] = ss;
        }
        __syncthreads();
    }
    float gmax = s_m[0];
    float inv = 1.f / s_s[0];

    for (int v = t; v < V_; v += 512) row[v] = __expf(row[v] - gmax) * inv;

    int id = ids[b];
    if (t < S_ && src[b * S_ + t] == id) atomicAdd(&s_cnt, 1);
    __syncthreads();

    if (t < S_) {
        float pc = __expf(s_lc[t] - gmax) * inv;
        atomicAdd(&row[src[b * S_ + t]], pc);
        float eq = (src[b * S_ + t] == id) ? 1.f : 0.f;
        s_att[t] = pc * eq / fmaxf((float)s_cnt, 1.f);
    }
    __syncthreads();

    // weighted_out: 512 threads, float2 each over 2H=1024 cols
    float2 acc = make_float2(0.f, 0.f);
    const float2* e2 = reinterpret_cast<const float2*>(enc + (size_t)b * S_ * (2 * H_));
    for (int sI = 0; sI < S_; sI++) {
        float w = s_att[sI];
        if (w != 0.f) {
            float2 e = e2[sI * 512 + t];
            acc.x = fmaf(w, e.x, acc.x);
            acc.y = fmaf(w, e.y, acc.y);
        }
    }
    reinterpret_cast<float2*>(outW)[b * 512 + t] = acc;
}

// ---------------- launch ----------------
extern "C" void kernel_launch(void* const* d_in, const int* in_sizes, int n_in,
                              void* d_out, int out_size) {
    const int*   input_ids = (const int*)d_in[0];
    const float* encoded   = (const float*)d_in[1];
    const int*   src       = (const int*)d_in[2];
    const float* prev      = (const float*)d_in[3];
    const float* weighted  = (const float*)d_in[4];
    const float* embed_w   = (const float*)d_in[6];
    const float* w_ih      = (const float*)d_in[7];
    const float* w_hh      = (const float*)d_in[8];
    const float* b_ih      = (const float*)d_in[9];
    const float* b_hh      = (const float*)d_in[10];
    const float* Wo_w      = (const float*)d_in[13];
    const float* Wo_b      = (const float*)d_in[14];
    const float* Wc_w      = (const float*)d_in[15];
    const float* Wc_b      = (const float*)d_in[16];

    float* pred        = (float*)d_out;
    float* outHidden   = pred + (size_t)B_ * V_;
    float* outWeighted = outHidden + (size_t)B_ * H_;

    cudaFuncSetAttribute(mma_gates, cudaFuncAttributeMaxDynamicSharedMemorySize, GATES_SMEM);
    cudaFuncSetAttribute(mma_scores, cudaFuncAttributeMaxDynamicSharedMemorySize, SCORES_SMEM);

    prep_kernel<<<PREP_CTAS, 256>>>(input_ids, embed_w, weighted, prev, Wc_w);

    mma_gates<<<GATES_CTAS, 256, GATES_SMEM>>>(b_ih, b_hh, w_ih, w_hh, encoded);

    gru_kernel<<<(B_ * H_) / 256, 256>>>(prev, outHidden);

    mma_scores<<<SC_CTAS + SG_CTAS, 256, SCORES_SMEM>>>(Wc_b, Wo_w, Wo_b, pred);

    softmax_weighted_kernel<<<B_, 512>>>(pred, src, input_ids, encoded, outWeighted);

    (void)in_sizes; (void)n_in; (void)out_size;
}

// round 17
// speedup vs baseline: 1.6335x; 1.0317x over previous
#include <cuda_runtime.h>
#include <cuda_fp16.h>
#include <math.h>
#include <stdint.h>

namespace {
constexpr int B_ = 256;
constexpr int S_ = 128;
constexpr int H_ = 512;
constexpr int E_ = 512;
constexpr int V_ = 32000;
constexpr int IN_ = E_ + 2 * H_;   // 1536
constexpr int G_ = 3 * H_;         // 1536
constexpr int NX_ = V_ / 128;      // 250
}

// ---------------- static scratch ----------------
__device__ float g_gi[B_ * G_];
__device__ float g_gh[B_ * G_];
__device__ float g_hidden[B_ * H_];
__device__ float g_sc[B_ * S_];
__device__ float g_pmax[B_ * NX_];
__device__ float g_psum[B_ * NX_];
__device__ __half g_x_hi[B_ * IN_];
__device__ __half g_x_lo[B_ * IN_];
__device__ __half g_prev_hi[B_ * H_];
__device__ __half g_prev_lo[B_ * H_];
__device__ __half g_wc_hi[H_ * 2 * H_];
__device__ __half g_enc_hi[B_ * S_ * 2 * H_];
__device__ __half g_hid_hi[B_ * H_];

// ---------------- helpers ----------------
__device__ __forceinline__ void cp_async16(uint32_t s, const void* g) {
    asm volatile("cp.async.cg.shared.global [%0], [%1], 16;\n"
                 :: "r"(s), "l"(g) : "memory");
}
__device__ __forceinline__ void cp_commit() {
    asm volatile("cp.async.commit_group;\n" ::: "memory");
}
template <int N>
__device__ __forceinline__ void cp_wait() {
    asm volatile("cp.async.wait_group %0;\n" :: "n"(N) : "memory");
}
__device__ __forceinline__ uint32_t smem_u32(const void* p) {
    uint32_t a;
    asm("{ .reg .u64 t; cvta.to.shared.u64 t, %1; cvt.u32.u64 %0, t; }"
        : "=r"(a) : "l"(p));
    return a;
}
__device__ __forceinline__ void ldmx4(uint32_t& r0, uint32_t& r1, uint32_t& r2,
                                      uint32_t& r3, uint32_t addr) {
    asm volatile("ldmatrix.sync.aligned.m8n8.x4.shared.b16 {%0,%1,%2,%3}, [%4];\n"
                 : "=r"(r0), "=r"(r1), "=r"(r2), "=r"(r3) : "r"(addr));
}
__device__ __forceinline__ void mma16816(float* d, const uint32_t* a,
                                         const uint32_t* b) {
    asm volatile(
        "mma.sync.aligned.m16n8k16.row.col.f32.f16.f16.f32 "
        "{%0,%1,%2,%3}, {%4,%5,%6,%7}, {%8,%9}, {%0,%1,%2,%3};\n"
        : "+f"(d[0]), "+f"(d[1]), "+f"(d[2]), "+f"(d[3])
        : "r"(a[0]), "r"(a[1]), "r"(a[2]), "r"(a[3]), "r"(b[0]), "r"(b[1]));
}
__device__ __forceinline__ uint32_t f2h2(float2 f) {
    __half2 h = __float22half2_rn(f);
    return *reinterpret_cast<uint32_t*>(&h);
}
__device__ __forceinline__ void split2h(float2 f, uint32_t& hi, uint32_t& lo) {
    hi = f2h2(f);
    __half2 hh = *reinterpret_cast<__half2*>(&hi);
    float2 fh = __half22float2(hh);
    lo = f2h2(make_float2(f.x - fh.x, f.y - fh.y));
}
__device__ __forceinline__ uint2 h4_of(float4 v) {
    return make_uint2(f2h2(make_float2(v.x, v.y)), f2h2(make_float2(v.z, v.w)));
}
__device__ __forceinline__ void hl4_of(float4 v, uint2& h, uint2& l) {
    uint32_t h0, h1, l0, l1;
    split2h(make_float2(v.x, v.y), h0, l0);
    split2h(make_float2(v.z, v.w), h1, l1);
    h = make_uint2(h0, h1); l = make_uint2(l0, l1);
}
__device__ __forceinline__ void msum(float& m, float& s, float om, float os) {
    float nm = fmaxf(m, om);
    s = s * __expf(m - nm) + os * __expf(om - nm);
    m = nm;
}

// =====================================================================
// Fused prep: x split, prev split, Wc hi, zero gi, zero sc
// =====================================================================
constexpr int PC0 = 96, PC1 = 32, PC4 = 512, PC5 = 96, PC6 = 8;
constexpr int PREP_CTAS = PC0 + PC1 + PC4 + PC5 + PC6;   // 744

__global__ void __launch_bounds__(256)
prep_kernel(const int* __restrict__ ids, const float* __restrict__ emb,
            const float* __restrict__ weighted, const float* __restrict__ prev,
            const float* __restrict__ Wc_w) {
    int bid = blockIdx.x;
    const int tid = threadIdx.x;
    if (bid < PC0) {
        const int n4 = B_ * IN_ / 4, T = PC0 * 256, J4 = IN_ / 4;
        for (int i = bid * 256 + tid; i < n4; i += T) {
            int b = i / J4, j = (i - b * J4) * 4;
            float4 v = (j < E_)
                ? *reinterpret_cast<const float4*>(emb + (size_t)ids[b] * E_ + j)
                : *reinterpret_cast<const float4*>(weighted + (size_t)b * 2 * H_ + (j - E_));
            uint2 h, l; hl4_of(v, h, l);
            *reinterpret_cast<uint2*>(g_x_hi + (size_t)i * 4) = h;
            *reinterpret_cast<uint2*>(g_x_lo + (size_t)i * 4) = l;
        }
        return;
    }
    bid -= PC0;
    if (bid < PC1) {
        const int n4 = B_ * H_ / 4, T = PC1 * 256;
        const float4* s4 = reinterpret_cast<const float4*>(prev);
        for (int i = bid * 256 + tid; i < n4; i += T) {
            uint2 h, l; hl4_of(s4[i], h, l);
            *reinterpret_cast<uint2*>(g_prev_hi + (size_t)i * 4) = h;
            *reinterpret_cast<uint2*>(g_prev_lo + (size_t)i * 4) = l;
        }
        return;
    }
    bid -= PC1;
    if (bid < PC4) {
        const int n4 = H_ * 2 * H_ / 4, T = PC4 * 256;
        const float4* s4 = reinterpret_cast<const float4*>(Wc_w);
        for (int i = bid * 256 + tid; i < n4; i += T)
            *reinterpret_cast<uint2*>(g_wc_hi + (size_t)i * 4) = h4_of(s4[i]);
        return;
    }
    bid -= PC4;
    if (bid < PC5) {
        const int n4 = B_ * G_ / 4, T = PC5 * 256;
        float4* p = reinterpret_cast<float4*>(g_gi);
        for (int i = bid * 256 + tid; i < n4; i += T)
            p[i] = make_float4(0.f, 0.f, 0.f, 0.f);
        return;
    }
    bid -= PC5;
    {
        const int n4 = B_ * S_ / 4, T = PC6 * 256;
        float4* p = reinterpret_cast<float4*>(g_sc);
        for (int i = bid * 256 + tid; i < n4; i += T)
            p[i] = make_float4(0.f, 0.f, 0.f, 0.f);
    }
}

// ---------------- common GEMM constants ----------------
constexpr int ROWB = 80;
constexpr int HTILE = 128 * ROWB;          // 10240 B (64B-row tiles)
constexpr int ROWC = 144;
constexpr int CTILE = 128 * ROWC;          // 18432 B (128B-row tiles)

// =====================================================================
// Gates + enc split in ONE launch (unchanged from R15/R16).
// =====================================================================
constexpr int GATES_GEMM = 96;
constexpr int GATES_SPLIT = 512;
constexpr int GATES_CTAS = GATES_GEMM + GATES_SPLIT;
constexpr uint32_t GT_B = 3 * 2 * HTILE;        // 61440
constexpr int GATES_SMEM = GT_B + 2 * HTILE;    // 81920

__global__ void __launch_bounds__(256, 2)
mma_gates(const float* __restrict__ b_ih, const float* __restrict__ b_hh,
          const float* __restrict__ w_ih, const float* __restrict__ w_hh,
          const float* __restrict__ enc) {
    extern __shared__ __align__(16) char smem[];
    const int t = threadIdx.x;

    if (blockIdx.x >= GATES_GEMM) {
        const int sbid = blockIdx.x - GATES_GEMM;
        const int n4 = B_ * S_ * 2 * H_ / 4;
        const int T = GATES_SPLIT * 256;
        const float4* s4 = reinterpret_cast<const float4*>(enc);
        uint2* h4 = reinterpret_cast<uint2*>(g_enc_hi);
        int i = sbid * 256 + t;
        for (; i + 3 * T < n4; i += 4 * T) {
            float4 v0 = s4[i], v1 = s4[i + T], v2 = s4[i + 2 * T], v3 = s4[i + 3 * T];
            h4[i] = h4_of(v0); h4[i + T] = h4_of(v1);
            h4[i + 2 * T] = h4_of(v2); h4[i + 3 * T] = h4_of(v3);
        }
        for (; i < n4; i += T) h4[i] = h4_of(s4[i]);
        return;
    }

    const int z = blockIdx.x / 24;
    const int rem = blockIdx.x % 24;
    const int by = rem / 12, bx = rem % 12;
    const int lane = t & 31;
    const int wid = t >> 5;
    const int wm = wid & 3, wn = wid >> 2;
    const int m0 = by * 128, n0 = bx * 128;
    const uint32_t sb = smem_u32(smem);

    const __half *Ah, *Al;
    const float *Bw, *bias;
    float* C;
    int K, kstart;
    bool atomic, addBias;
    if (z < 3) {
        Ah = g_x_hi; Al = g_x_lo; Bw = w_ih;
        bias = b_ih; C = g_gi; K = IN_; kstart = z * 512;
        atomic = true; addBias = (z == 0);
    } else {
        Ah = g_prev_hi; Al = g_prev_lo; Bw = w_hh;
        bias = b_hh; C = g_gh; K = H_; kstart = 0;
        atomic = false; addBias = true;
    }
    const int KCH = 16;

    float acc[2][8][4];
#pragma unroll
    for (int i = 0; i < 2; i++)
#pragma unroll
        for (int j = 0; j < 8; j++)
#pragma unroll
            for (int r = 0; r < 4; r++) acc[i][j][r] = 0.f;

    const int br = t >> 1, bhf = t & 1;
    const float* Bbase = Bw + (size_t)(n0 + br) * K + kstart + bhf * 16;

    float4 r4[4];
    auto ldgB = [&](int it) {
        const float* p = Bbase + it * 32;
#pragma unroll
        for (int i = 0; i < 4; i++) r4[i] = *reinterpret_cast<const float4*>(p + i * 4);
    };
    auto stsB = [&](int buf) {
        uint32_t h[8];
#pragma unroll
        for (int i = 0; i < 4; i++) {
            h[i * 2]     = f2h2(make_float2(r4[i].x, r4[i].y));
            h[i * 2 + 1] = f2h2(make_float2(r4[i].z, r4[i].w));
        }
        uint32_t d = GT_B + (uint32_t)buf * HTILE + (uint32_t)(br * ROWB + bhf * 32);
        *reinterpret_cast<uint4*>(smem + d)      = make_uint4(h[0], h[1], h[2], h[3]);
        *reinterpret_cast<uint4*>(smem + d + 16) = make_uint4(h[4], h[5], h[6], h[7]);
    };
    auto issueA = [&](int it) {
        uint32_t ring = sb + (uint32_t)(it % 3) * (2 * HTILE);
        int kk = kstart + it * 32;
#pragma unroll
        for (int i = 0; i < 2; i++) {
            int idx = t + i * 256;
            int row = idx >> 2, col = idx & 3;
            uint32_t so = (uint32_t)(row * ROWB + col * 16);
            const size_t ga = (size_t)(m0 + row) * K + kk + col * 8;
            cp_async16(ring + so, Ah + ga);
            cp_async16(ring + HTILE + so, Al + ga);
        }
        cp_commit();
    };

    const int a_row = (lane & 15);
    const int a_kof = ((lane >> 4) & 1) * 16;
    const int b_row = ((lane >> 4) << 3) + (lane & 7);
    const int b_kof = ((lane >> 3) & 1) * 16;
    const int g = lane >> 2, q = lane & 3;

    issueA(0); issueA(1);
    ldgB(0);
    cp_wait<1>();
    stsB(0);
    __syncthreads();

    for (int it = 0; it < KCH; ++it) {
        if (it + 1 < KCH) ldgB(it + 1);
        if (it + 2 < KCH) issueA(it + 2);

        const uint32_t ring = sb + (uint32_t)(it % 3) * (2 * HTILE);
        const uint32_t bT = GT_B + (uint32_t)(it & 1) * HTILE;
#pragma unroll
        for (int ks = 0; ks < 2; ks++) {
            const int kb = ks * 32;
            uint32_t bh[8][2];
#pragma unroll
            for (int njp = 0; njp < 4; njp++) {
                uint32_t addr = sb + bT + (wn * 64 + njp * 16 + b_row) * ROWB + kb + b_kof;
                uint32_t q0, q1, q2, q3;
                ldmx4(q0, q1, q2, q3, addr);
                bh[njp * 2][0] = q0; bh[njp * 2][1] = q1;
                bh[njp * 2 + 1][0] = q2; bh[njp * 2 + 1][1] = q3;
            }
#pragma unroll
            for (int mi = 0; mi < 2; mi++) {
                const uint32_t aro = (wm * 32 + mi * 16 + a_row) * ROWB + kb + a_kof;
                uint32_t ah[4], al[4];
                ldmx4(ah[0], ah[1], ah[2], ah[3], ring + aro);
                ldmx4(al[0], al[1], al[2], al[3], ring + HTILE + aro);
#pragma unroll
                for (int nj = 0; nj < 8; nj++) mma16816(acc[mi][nj], ah, bh[nj]);
#pragma unroll
                for (int nj = 0; nj < 8; nj++) mma16816(acc[mi][nj], al, bh[nj]);
            }
        }
        if (it + 1 < KCH) {
            if (it + 2 < KCH) cp_wait<1>(); else cp_wait<0>();
            stsB((it + 1) & 1);
        }
        __syncthreads();
    }

#pragma unroll
    for (int mi = 0; mi < 2; mi++) {
        int row0 = m0 + wm * 32 + mi * 16 + g;
        int row1 = row0 + 8;
#pragma unroll
        for (int nj = 0; nj < 8; nj++) {
            int col = n0 + wn * 64 + nj * 8 + 2 * q;
            float b0 = addBias ? bias[col] : 0.f;
            float b1 = addBias ? bias[col + 1] : 0.f;
            if (atomic) {
                atomicAdd(&C[(size_t)row0 * G_ + col],     acc[mi][nj][0] + b0);
                atomicAdd(&C[(size_t)row0 * G_ + col + 1], acc[mi][nj][1] + b1);
                atomicAdd(&C[(size_t)row1 * G_ + col],     acc[mi][nj][2] + b0);
                atomicAdd(&C[(size_t)row1 * G_ + col + 1], acc[mi][nj][3] + b1);
            } else {
                float2 o0 = make_float2(acc[mi][nj][0] + b0, acc[mi][nj][1] + b1);
                float2 o1 = make_float2(acc[mi][nj][2] + b0, acc[mi][nj][3] + b1);
                *reinterpret_cast<float2*>(&C[(size_t)row0 * G_ + col]) = o0;
                *reinterpret_cast<float2*>(&C[(size_t)row1 * G_ + col]) = o1;
            }
        }
    }
}

// =====================================================================
// Merged scores kernel.
// sc: K-chunk 64 (128B rows, stride 144), 3-stage rings, 16 iters.
// sg: K-chunk 32 (unchanged).
// =====================================================================
constexpr uint32_t SG_B = 3 * HTILE;
constexpr int SG_SMEM = SG_B + 2 * HTILE;       // 51200
constexpr uint32_t SC_B = 3 * CTILE;            // 55296
constexpr int SC_SMEM = SC_B + 3 * CTILE;       // 110592
constexpr int SCORES_SMEM = SC_SMEM;
constexpr int SC_CTAS = 4 * 256;                // 1024
constexpr int SG_CTAS = NX_ * 2;                // 500

__device__ void sg_body(char* smem, int bx, int by,
                        const __half* __restrict__ Ah,
                        const float* __restrict__ Bf, const float* __restrict__ bias,
                        float* __restrict__ C) {
    const int K = H_, N = V_;
    const int t = threadIdx.x;
    const int lane = t & 31;
    const int wid = t >> 5;
    const int wm = wid & 3, wn = wid >> 2;
    const int m0 = by * 128, n0 = bx * 128;
    const uint32_t sb = smem_u32(smem);

    float acc[2][8][4];
#pragma unroll
    for (int i = 0; i < 2; i++)
#pragma unroll
        for (int j = 0; j < 8; j++)
#pragma unroll
            for (int r = 0; r < 4; r++) acc[i][j][r] = 0.f;

    const int KT = K / 32;   // 16
    const int br = t >> 1, bhf = t & 1;
    const float* Bbase = Bf + (size_t)(n0 + br) * K + bhf * 16;

    float4 r4[4];
    auto ldgB = [&](int it) {
        const float* p = Bbase + it * 32;
#pragma unroll
        for (int i = 0; i < 4; i++) r4[i] = *reinterpret_cast<const float4*>(p + i * 4);
    };
    auto stsB = [&](int buf) {
        uint32_t h[8];
#pragma unroll
        for (int i = 0; i < 4; i++) {
            h[i * 2]     = f2h2(make_float2(r4[i].x, r4[i].y));
            h[i * 2 + 1] = f2h2(make_float2(r4[i].z, r4[i].w));
        }
        uint32_t d = SG_B + (uint32_t)buf * HTILE + (uint32_t)(br * ROWB + bhf * 32);
        *reinterpret_cast<uint4*>(smem + d)      = make_uint4(h[0], h[1], h[2], h[3]);
        *reinterpret_cast<uint4*>(smem + d + 16) = make_uint4(h[4], h[5], h[6], h[7]);
    };
    auto issueA = [&](int it) {
        uint32_t ring = sb + (uint32_t)(it % 3) * HTILE;
        int kk = it * 32;
#pragma unroll
        for (int i = 0; i < 2; i++) {
            int idx = t + i * 256;
            int row = idx >> 2, col = idx & 3;
            uint32_t so = (uint32_t)(row * ROWB + col * 16);
            cp_async16(ring + so, Ah + (size_t)(m0 + row) * K + kk + col * 8);
        }
        cp_commit();
    };

    const int a_row = (lane & 15);
    const int a_kof = ((lane >> 4) & 1) * 16;
    const int b_row = ((lane >> 4) << 3) + (lane & 7);
    const int b_kof = ((lane >> 3) & 1) * 16;
    const int g = lane >> 2, q = lane & 3;

    issueA(0); issueA(1);
    ldgB(0);
    cp_wait<1>();
    stsB(0);
    __syncthreads();

    for (int it = 0; it < KT; ++it) {
        if (it + 1 < KT) ldgB(it + 1);
        if (it + 2 < KT) issueA(it + 2);

        const uint32_t ring = sb + (uint32_t)(it % 3) * HTILE;
        const uint32_t bT = SG_B + (uint32_t)(it & 1) * HTILE;
#pragma unroll
        for (int ks = 0; ks < 2; ks++) {
            const int kb = ks * 32;
            uint32_t bh[8][2];
#pragma unroll
            for (int njp = 0; njp < 4; njp++) {
                uint32_t addr = sb + bT + (wn * 64 + njp * 16 + b_row) * ROWB + kb + b_kof;
                uint32_t q0, q1, q2, q3;
                ldmx4(q0, q1, q2, q3, addr);
                bh[njp * 2][0] = q0; bh[njp * 2][1] = q1;
                bh[njp * 2 + 1][0] = q2; bh[njp * 2 + 1][1] = q3;
            }
#pragma unroll
            for (int mi = 0; mi < 2; mi++) {
                const uint32_t aro = (wm * 32 + mi * 16 + a_row) * ROWB + kb + a_kof;
                uint32_t ah[4];
                ldmx4(ah[0], ah[1], ah[2], ah[3], ring + aro);
#pragma unroll
                for (int nj = 0; nj < 8; nj++) mma16816(acc[mi][nj], ah, bh[nj]);
            }
        }
        if (it + 1 < KT) {
            if (it + 2 < KT) cp_wait<1>(); else cp_wait<0>();
            stsB((it + 1) & 1);
        }
        __syncthreads();
    }

    float pm[4], ps[4];
#pragma unroll
    for (int mi = 0; mi < 2; mi++) {
        float m0v = -1e30f, s0v = 0.f, m1v = -1e30f, s1v = 0.f;
        int row0 = m0 + wm * 32 + mi * 16 + g;
        int row1 = row0 + 8;
#pragma unroll
        for (int nj = 0; nj < 8; nj++) {
            int col = n0 + wn * 64 + nj * 8 + 2 * q;
            float b0 = bias[col], b1 = bias[col + 1];
            float v00 = acc[mi][nj][0] + b0, v01 = acc[mi][nj][1] + b1;
            float v10 = acc[mi][nj][2] + b0, v11 = acc[mi][nj][3] + b1;
            *reinterpret_cast<float2*>(&C[(size_t)row0 * N + col]) = make_float2(v00, v01);
            *reinterpret_cast<float2*>(&C[(size_t)row1 * N + col]) = make_float2(v10, v11);
            msum(m0v, s0v, v00, 1.f); msum(m0v, s0v, v01, 1.f);
            msum(m1v, s1v, v10, 1.f); msum(m1v, s1v, v11, 1.f);
        }
#pragma unroll
        for (int off = 1; off <= 2; off <<= 1) {
            float om = __shfl_xor_sync(0xffffffffu, m0v, off);
            float os = __shfl_xor_sync(0xffffffffu, s0v, off);
            msum(m0v, s0v, om, os);
            om = __shfl_xor_sync(0xffffffffu, m1v, off);
            os = __shfl_xor_sync(0xffffffffu, s1v, off);
            msum(m1v, s1v, om, os);
        }
        pm[mi * 2] = m0v; ps[mi * 2] = s0v;
        pm[mi * 2 + 1] = m1v; ps[mi * 2 + 1] = s1v;
    }
    __syncthreads();
    float* s_pm = reinterpret_cast<float*>(smem);
    float* s_ps = reinterpret_cast<float*>(smem + 512);
    if (wn == 0 && q == 0) {
#pragma unroll
        for (int i = 0; i < 4; i++) {
            int r_in = wm * 32 + (i >> 1) * 16 + g + (i & 1) * 8;
            s_pm[r_in] = pm[i]; s_ps[r_in] = ps[i];
        }
    }
    __syncthreads();
    if (wn == 1 && q == 0) {
#pragma unroll
        for (int i = 0; i < 4; i++) {
            int r_in = wm * 32 + (i >> 1) * 16 + g + (i & 1) * 8;
            float m = pm[i], s = ps[i];
            msum(m, s, s_pm[r_in], s_ps[r_in]);
            g_pmax[(size_t)(m0 + r_in) * NX_ + bx] = m;
            g_psum[(size_t)(m0 + r_in) * NX_ + bx] = s;
        }
    }
}

__device__ void sc_body(char* smem, int bx, int by,
                        const __half* __restrict__ Ah, const __half* __restrict__ Bh16,
                        const float* __restrict__ bias,
                        const float* __restrict__ hidden, float* __restrict__ scOut) {
    const int K = 2 * H_;   // 1024
    const int t = threadIdx.x;
    const int lane = t & 31;
    const int wid = t >> 5;
    const int wm = wid & 3, wn = wid >> 2;
    const int m0 = by * 128, n0 = bx * 128;
    const uint32_t sb = smem_u32(smem);

    float acc[2][8][4];
#pragma unroll
    for (int i = 0; i < 2; i++)
#pragma unroll
        for (int j = 0; j < 8; j++)
#pragma unroll
            for (int r = 0; r < 4; r++) acc[i][j][r] = 0.f;

    const int KT = K / 64;   // 16 iterations of 64-wide K chunks

    auto issue = [&](int it) {
        uint32_t ringA = sb + (uint32_t)(it % 3) * CTILE;
        uint32_t ringB = sb + SC_B + (uint32_t)(it % 3) * CTILE;
        int kk = it * 64;
#pragma unroll
        for (int i = 0; i < 4; i++) {
            int idx = t + i * 256;
            int row = idx >> 3, col = idx & 7;
            uint32_t so = (uint32_t)(row * ROWC + col * 16);
            cp_async16(ringA + so, Ah + (size_t)(m0 + row) * K + kk + col * 8);
            cp_async16(ringB + so, Bh16 + (size_t)(n0 + row) * K + kk + col * 8);
        }
        cp_commit();
    };

    const int a_row = (lane & 15);
    const int a_kof = ((lane >> 4) & 1) * 16;
    const int b_row = ((lane >> 4) << 3) + (lane & 7);
    const int b_kof = ((lane >> 3) & 1) * 16;
    const int g = lane >> 2, q = lane & 3;

    issue(0); issue(1);
    for (int it = 0; it < KT; ++it) {
        if (it + 1 < KT) cp_wait<1>(); else cp_wait<0>();
        __syncthreads();
        if (it + 2 < KT) issue(it + 2);

        const uint32_t aT = sb + (uint32_t)(it % 3) * CTILE;
        const uint32_t bT = sb + SC_B + (uint32_t)(it % 3) * CTILE;
#pragma unroll
        for (int ks = 0; ks < 4; ks++) {
            const int kb = ks * 32;
            uint32_t bh[8][2];
#pragma unroll
            for (int njp = 0; njp < 4; njp++) {
                uint32_t addr = bT + (wn * 64 + njp * 16 + b_row) * ROWC + kb + b_kof;
                uint32_t q0, q1, q2, q3;
                ldmx4(q0, q1, q2, q3, addr);
                bh[njp * 2][0] = q0; bh[njp * 2][1] = q1;
                bh[njp * 2 + 1][0] = q2; bh[njp * 2 + 1][1] = q3;
            }
#pragma unroll
            for (int mi = 0; mi < 2; mi++) {
                const uint32_t aro = (wm * 32 + mi * 16 + a_row) * ROWC + kb + a_kof;
                uint32_t ah[4];
                ldmx4(ah[0], ah[1], ah[2], ah[3], aT + aro);
#pragma unroll
                for (int nj = 0; nj < 8; nj++) mma16816(acc[mi][nj], ah, bh[nj]);
            }
        }
    }

    const int b = m0 >> 7;
#pragma unroll
    for (int mi = 0; mi < 2; mi++) {
        float p0 = 0.f, p1 = 0.f;
#pragma unroll
        for (int nj = 0; nj < 8; nj++) {
            int col = n0 + wn * 64 + nj * 8 + 2 * q;
            float bz0 = bias[col], bz1 = bias[col + 1];
            float hv0 = hidden[b * H_ + col], hv1 = hidden[b * H_ + col + 1];
            p0 = fmaf(tanhf(acc[mi][nj][0] + bz0), hv0, p0);
            p0 = fmaf(tanhf(acc[mi][nj][1] + bz1), hv1, p0);
            p1 = fmaf(tanhf(acc[mi][nj][2] + bz0), hv0, p1);
            p1 = fmaf(tanhf(acc[mi][nj][3] + bz1), hv1, p1);
        }
        p0 += __shfl_xor_sync(0xffffffffu, p0, 1);
        p0 += __shfl_xor_sync(0xffffffffu, p0, 2);
        p1 += __shfl_xor_sync(0xffffffffu, p1, 1);
        p1 += __shfl_xor_sync(0xffffffffu, p1, 2);
        if (q == 0) {
            int row = m0 + wm * 32 + mi * 16 + g;
            atomicAdd(&scOut[row], p0);
            atomicAdd(&scOut[row + 8], p1);
        }
    }
}

__global__ void __launch_bounds__(256, 2)
mma_scores(const float* __restrict__ Wc_b,
           const float* __restrict__ Wo_w, const float* __restrict__ Wo_b,
           float* __restrict__ pred) {
    extern __shared__ __align__(16) char smem[];
    const int bid = blockIdx.x;
    if (bid < SC_CTAS) {
        sc_body(smem, bid & 3, bid >> 2, g_enc_hi, g_wc_hi, Wc_b, g_hidden, g_sc);
    } else {
        int id = bid - SC_CTAS;
        sg_body(smem, id % NX_, id / NX_, g_hid_hi, Wo_w, Wo_b, pred);
    }
}

// ---------------- GRU ----------------
__global__ void gru_kernel(const float* __restrict__ prev,
                           float* __restrict__ outHidden) {
    int idx = blockIdx.x * blockDim.x + threadIdx.x;
    int b = idx >> 9, h = idx & (H_ - 1);
    const float* gi = g_gi + (size_t)b * G_;
    const float* gh = g_gh + (size_t)b * G_;
    float ir = gi[h], iz = gi[h + H_], inn = gi[h + 2 * H_];
    float hr = gh[h], hz = gh[h + H_], hn = gh[h + 2 * H_];
    float r = 1.f / (1.f + expf(-(ir + hr)));
    float z = 1.f / (1.f + expf(-(iz + hz)));
    float n = tanhf(inn + r * hn);
    float hv = (1.f - z) * n + z * prev[idx];
    g_hidden[idx] = hv;
    outHidden[idx] = hv;
    g_hid_hi[idx] = __float2half_rn(hv);
}

// ---------------- softmax + weighted_out (merged) ----------------
__global__ void __launch_bounds__(512)
softmax_weighted_kernel(float* __restrict__ pred, const int* __restrict__ src,
                        const int* __restrict__ ids,
                        const float* __restrict__ enc,
                        float* __restrict__ outW) {
    __shared__ float s_lc[S_];
    __shared__ float s_att[S_];
    __shared__ float s_m[512];
    __shared__ float s_s[512];
    __shared__ int s_cnt;
    const int b = blockIdx.x, t = threadIdx.x;
    float* row = pred + (size_t)b * V_;

    if (t == 0) s_cnt = 0;
    if (t < S_) {
        float mask = (src[b * S_ + t] == 0) ? -1000.f : 0.f;
        s_lc[t] = tanhf(g_sc[b * S_ + t] + mask);
    }
    __syncthreads();

    float m = -1e30f, s = 0.f;
    for (int x = t; x < NX_; x += 512)
        msum(m, s, g_pmax[(size_t)b * NX_ + x], g_psum[(size_t)b * NX_ + x]);
    if (t < S_) msum(m, s, s_lc[t], 1.f);
    s_m[t] = m; s_s[t] = s;
    __syncthreads();
    for (int o = 256; o; o >>= 1) {
        if (t < o) {
            float mm = s_m[t], ss = s_s[t];
            msum(mm, ss, s_m[t + o], s_s[t + o]);
            s_m[t] = mm; s_s[t] = ss;
        }
        __syncthreads();
    }
    float gmax = s_m[0];
    float inv = 1.f / s_s[0];

    for (int v = t; v < V_; v += 512) row[v] = __expf(row[v] - gmax) * inv;

    int id = ids[b];
    if (t < S_ && src[b * S_ + t] == id) atomicAdd(&s_cnt, 1);
    __syncthreads();

    if (t < S_) {
        float pc = __expf(s_lc[t] - gmax) * inv;
        atomicAdd(&row[src[b * S_ + t]], pc);
        float eq = (src[b * S_ + t] == id) ? 1.f : 0.f;
        s_att[t] = pc * eq / fmaxf((float)s_cnt, 1.f);
    }
    __syncthreads();

    float2 acc = make_float2(0.f, 0.f);
    const float2* e2 = reinterpret_cast<const float2*>(enc + (size_t)b * S_ * (2 * H_));
    for (int sI = 0; sI < S_; sI++) {
        float w = s_att[sI];
        if (w != 0.f) {
            float2 e = e2[sI * 512 + t];
            acc.x = fmaf(w, e.x, acc.x);
            acc.y = fmaf(w, e.y, acc.y);
        }
    }
    reinterpret_cast<float2*>(outW)[b * 512 + t] = acc;
}

// ---------------- launch ----------------
extern "C" void kernel_launch(void* const* d_in, const int* in_sizes, int n_in,
                              void* d_out, int out_size) {
    const int*   input_ids = (const int*)d_in[0];
    const float* encoded   = (const float*)d_in[1];
    const int*   src       = (const int*)d_in[2];
    const float* prev      = (const float*)d_in[3];
    const float* weighted  = (const float*)d_in[4];
    const float* embed_w   = (const float*)d_in[6];
    const float* w_ih      = (const float*)d_in[7];
    const float* w_hh      = (const float*)d_in[8];
    const float* b_ih      = (const float*)d_in[9];
    const float* b_hh      = (const float*)d_in[10];
    const float* Wo_w      = (const float*)d_in[13];
    const float* Wo_b      = (const float*)d_in[14];
    const float* Wc_w      = (const float*)d_in[15];
    const float* Wc_b      = (const float*)d_in[16];

    float* pred        = (float*)d_out;
    float* outHidden   = pred + (size_t)B_ * V_;
    float* outWeighted = outHidden + (size_t)B_ * H_;

    cudaFuncSetAttribute(mma_gates, cudaFuncAttributeMaxDynamicSharedMemorySize, GATES_SMEM);
    cudaFuncSetAttribute(mma_scores, cudaFuncAttributeMaxDynamicSharedMemorySize, SCORES_SMEM);

    prep_kernel<<<PREP_CTAS, 256>>>(input_ids, embed_w, weighted, prev, Wc_w);

    mma_gates<<<GATES_CTAS, 256, GATES_SMEM>>>(b_ih, b_hh, w_ih, w_hh, encoded);

    gru_kernel<<<(B_ * H_) / 256, 256>>>(prev, outHidden);

    mma_scores<<<SC_CTAS + SG_CTAS, 256, SCORES_SMEM>>>(Wc_b, Wo_w, Wo_b, pred);

    softmax_weighted_kernel<<<B_, 512>>>(pred, src, input_ids, encoded, outWeighted);

    (void)in_sizes; (void)n_in; (void)out_size;
}